// round 1
// baseline (speedup 1.0000x reference)
#include <cuda_runtime.h>
#include <math.h>

// Problem constants
#define LSEQ 256
#define BB   64
#define DD   1024
#define HH   512
#define RR   8
#define CC   6
#define NTOT 16384          // B*L
#define DHE  1536           // D + H
#define WINR 10
#define WSZ  21             // 2*WIN+1
#define HA_COLS 4608        // 9 * 512  (8 relations + root)

// ---------------- scratch (device globals; no allocation) ----------------
__device__ float g_x  [(size_t)NTOT * DD];
__device__ float g_P  [(size_t)NTOT * LSEQ];
__device__ float g_EW [(size_t)BB * LSEQ * WSZ];
__device__ float g_HA [(size_t)NTOT * HA_COLS];
__device__ float g_h1 [(size_t)NTOT * HH];
__device__ float g_nbr[(size_t)NTOT * HH];
__device__ float g_h2 [(size_t)NTOT * HH];
__device__ float g_em [(size_t)NTOT * DHE];
__device__ float g_XT [(size_t)NTOT * DHE];
__device__ float g_S  [(size_t)BB * LSEQ * LSEQ];
__device__ float g_ATT[(size_t)NTOT * DHE];
__device__ float g_HID[(size_t)NTOT * HH];

// ---------------- generic fp32 SGEMM: C = A @ B(^T) ----------------
// 128x128 block tile, BK=8, 256 threads, 8x8 microtile.
// Requires M%128==0, N%128==0, K%8==0 (all shapes here satisfy this).
// ACT: 0 none, 1 relu, 2 tanh.  ACC: C += result.  BIAS: add bias[col].
template<int ACT, bool BT, bool ACC, bool BIAS>
__global__ __launch_bounds__(256) void sgemm(
    const float* __restrict__ A, const float* __restrict__ B,
    float* __restrict__ C, const float* __restrict__ bias,
    int M, int N, int K, int lda, int ldb, int ldc,
    long long sA, long long sB, long long sC)
{
    A += (long long)blockIdx.z * sA;
    B += (long long)blockIdx.z * sB;
    C += (long long)blockIdx.z * sC;

    __shared__ float As[8][128];
    __shared__ float Bs[8][128];

    const int tid = threadIdx.x;
    const int tx = tid & 15;          // 0..15  -> 8 cols each
    const int ty = tid >> 4;          // 0..15  -> 8 rows each
    const int m0 = blockIdx.y * 128;
    const int n0 = blockIdx.x * 128;

    const int arow = tid >> 1;        // 0..127
    const int aseg = tid & 1;         // 0/1 (float4 segment)
    const int brow = tid >> 5;        // 0..7
    const int bcol = (tid & 31) * 4;  // 0..124

    float acc[8][8];
    #pragma unroll
    for (int i = 0; i < 8; i++)
        #pragma unroll
        for (int j = 0; j < 8; j++) acc[i][j] = 0.f;

    for (int k0 = 0; k0 < K; k0 += 8) {
        // A tile (transposed store)
        {
            const float4 v = *(const float4*)(A + (long long)(m0 + arow) * lda + k0 + aseg * 4);
            As[aseg*4+0][arow] = v.x; As[aseg*4+1][arow] = v.y;
            As[aseg*4+2][arow] = v.z; As[aseg*4+3][arow] = v.w;
        }
        if (!BT) {
            const float4 v = *(const float4*)(B + (long long)(k0 + brow) * ldb + n0 + bcol);
            *(float4*)(&Bs[brow][bcol]) = v;
        } else {
            // B row-major [N,K]; need Bs[k][n]
            const float4 v = *(const float4*)(B + (long long)(n0 + arow) * ldb + k0 + aseg * 4);
            Bs[aseg*4+0][arow] = v.x; Bs[aseg*4+1][arow] = v.y;
            Bs[aseg*4+2][arow] = v.z; Bs[aseg*4+3][arow] = v.w;
        }
        __syncthreads();

        #pragma unroll
        for (int kk = 0; kk < 8; kk++) {
            float a[8], b[8];
            #pragma unroll
            for (int i = 0; i < 8; i++) a[i] = As[kk][ty*8 + i];
            #pragma unroll
            for (int j = 0; j < 8; j++) b[j] = Bs[kk][tx*8 + j];
            #pragma unroll
            for (int i = 0; i < 8; i++)
                #pragma unroll
                for (int j = 0; j < 8; j++)
                    acc[i][j] += a[i] * b[j];
        }
        __syncthreads();
    }

    #pragma unroll
    for (int i = 0; i < 8; i++) {
        const long long row = m0 + ty*8 + i;
        #pragma unroll
        for (int j = 0; j < 8; j++) {
            const int col = n0 + tx*8 + j;
            float v = acc[i][j];
            if (ACC)  v += C[row * ldc + col];
            if (BIAS) v += bias[col];
            if (ACT == 1) v = fmaxf(v, 0.f);
            if (ACT == 2) v = tanhf(v);
            C[row * ldc + col] = v;
        }
    }
}

// ---------------- stage kernels ----------------

// x[(b*L+s), d] = features[s, b, d]
__global__ void make_x_kernel(const float* __restrict__ f)
{
    const int n = blockIdx.x;               // b*256 + s
    const int b = n >> 8, s = n & 255;
    const float* src = f + ((long long)s * BB + b) * DD;
    float* dst = g_x + (long long)n * DD;
    for (int d = threadIdx.x; d < DD; d += blockDim.x) dst[d] = src[d];
}

// Per (b, anchor i): softmax over s of P[(b,s), i], windowed renorm, emit 21 weights.
__global__ void edge_softmax_kernel()
{
    __shared__ float red[256];
    const int bi = blockIdx.x;              // b*256 + i
    const int b = bi >> 8, i = bi & 255;
    const int s = threadIdx.x;

    const float v = g_P[((long long)(b * 256 + s)) * LSEQ + i];

    red[s] = v; __syncthreads();
    for (int o = 128; o > 0; o >>= 1) { if (s < o) red[s] = fmaxf(red[s], red[s + o]); __syncthreads(); }
    const float m = red[0]; __syncthreads();

    const float e = __expf(v - m);
    red[s] = e; __syncthreads();
    for (int o = 128; o > 0; o >>= 1) { if (s < o) red[s] += red[s + o]; __syncthreads(); }
    const float Z = red[0]; __syncthreads();

    const bool inwin = (s >= i - WINR) && (s <= i + WINR);
    red[s] = inwin ? e : 0.f; __syncthreads();
    for (int o = 128; o > 0; o >>= 1) { if (s < o) red[s] += red[s + o]; __syncthreads(); }
    const float Swin = red[0];

    const float denom = Swin + 1e-10f * (Z - Swin);
    if (inwin)
        g_EW[(long long)bi * WSZ + (s - i + WINR)] = e / denom;
    if (s < WSZ) {
        const int k = i - WINR + s;
        if (k < 0 || k >= LSEQ) g_EW[(long long)bi * WSZ + s] = 0.f;
    }
}

// h1[n=(b,k), h] = HA_root + b_rgcn + sum_{i in win(k)} w(b,i,k) * HA[(b,i), rel, h]
__global__ __launch_bounds__(512) void rgcn_agg_kernel(
    const int* __restrict__ speakers, const float* __restrict__ b_rgcn)
{
    const int n = blockIdx.x;
    const int b = n >> 8, k = n & 255;
    const int h = threadIdx.x;

    __shared__ int   sp[WSZ];
    __shared__ float w [WSZ];
    const int lo = max(k - WINR, 0), hi = min(k + WINR, LSEQ - 1);
    const int cnt = hi - lo + 1;
    if (h < cnt) {
        const int i = lo + h;
        sp[h] = speakers[i * BB + b];
        w [h] = g_EW[((long long)(b * 256 + i)) * WSZ + (k - i + WINR)];
    }
    __syncthreads();

    const int spk = sp[k - lo];            // k is always inside its own window
    float acc = g_HA[(long long)n * HA_COLS + 4096 + h] + b_rgcn[h];
    for (int t = 0; t < cnt; t++) {
        const int i = lo + t;
        const int rel = sp[t] * 4 + spk * 2 + ((i < k) ? 0 : 1);
        acc += w[t] * g_HA[((long long)(b * 256 + i)) * HA_COLS + rel * HH + h];
    }
    g_h1[(long long)n * HH + h] = acc;
}

// Sliding-window neighbor sum: nbr[b,k,h] = sum_{j in [k-10,k+10]} h1[b,j,h]
__global__ __launch_bounds__(512) void nbr_kernel()
{
    const int b = blockIdx.x;
    const int kstart = blockIdx.y * 64;
    const int h = threadIdx.x;

    float run = 0.f;
    const int lo = max(kstart - WINR, 0), hi = min(kstart + WINR, LSEQ - 1);
    for (int j = lo; j <= hi; j++) run += g_h1[((long long)(b * 256 + j)) * HH + h];
    g_nbr[((long long)(b * 256 + kstart)) * HH + h] = run;

    for (int k = kstart + 1; k < kstart + 64; k++) {
        const int add = k + WINR, sub = k - WINR - 1;
        if (add < LSEQ) run += g_h1[((long long)(b * 256 + add)) * HH + h];
        if (sub >= 0)   run -= g_h1[((long long)(b * 256 + sub)) * HH + h];
        g_nbr[((long long)(b * 256 + k)) * HH + h] = run;
    }
}

// em = concat(x, h2)
__global__ void build_em_kernel()
{
    const int n = blockIdx.x;
    float* dst = g_em + (long long)n * DHE;
    const float* xs = g_x + (long long)n * DD;
    const float* hs = g_h2 + (long long)n * HH;
    for (int d = threadIdx.x; d < DD; d += blockDim.x) dst[d] = xs[d];
    for (int d = threadIdx.x; d < HH; d += blockDim.x) dst[DD + d] = hs[d];
}

// Row softmax over contiguous 256-length rows of g_S (already tanh'd)
__global__ void softmax_rows_kernel()
{
    __shared__ float red[256];
    const long long r = blockIdx.x;
    const int s = threadIdx.x;
    const float v = g_S[r * 256 + s];

    red[s] = v; __syncthreads();
    for (int o = 128; o > 0; o >>= 1) { if (s < o) red[s] = fmaxf(red[s], red[s + o]); __syncthreads(); }
    const float m = red[0]; __syncthreads();
    const float e = __expf(v - m);
    red[s] = e; __syncthreads();
    for (int o = 128; o > 0; o >>= 1) { if (s < o) red[s] += red[s + o]; __syncthreads(); }
    g_S[r * 256 + s] = e / red[0];
}

// logits = HID @ W_fc + b_fc ; out = log_softmax(logits).  One warp per node.
__global__ void final_kernel(const float* __restrict__ W_fc,
                             const float* __restrict__ b_fc,
                             float* __restrict__ out)
{
    const int gwarp = (blockIdx.x * blockDim.x + threadIdx.x) >> 5;
    const int lane = threadIdx.x & 31;
    if (gwarp >= NTOT) return;

    float p[CC] = {0.f, 0.f, 0.f, 0.f, 0.f, 0.f};
    #pragma unroll
    for (int j = 0; j < 16; j++) {
        const int hidx = lane + j * 32;
        const float hv = g_HID[(long long)gwarp * HH + hidx];
        const float* wr = W_fc + (long long)hidx * CC;
        #pragma unroll
        for (int c = 0; c < CC; c++) p[c] += hv * wr[c];
    }
    #pragma unroll
    for (int o = 16; o > 0; o >>= 1)
        #pragma unroll
        for (int c = 0; c < CC; c++) p[c] += __shfl_down_sync(0xffffffffu, p[c], o);

    if (lane == 0) {
        float lg[CC], m = -1e30f;
        #pragma unroll
        for (int c = 0; c < CC; c++) { lg[c] = p[c] + b_fc[c]; m = fmaxf(m, lg[c]); }
        float ssum = 0.f;
        #pragma unroll
        for (int c = 0; c < CC; c++) ssum += __expf(lg[c] - m);
        const float lse = m + logf(ssum);
        #pragma unroll
        for (int c = 0; c < CC; c++) out[(long long)gwarp * CC + c] = lg[c] - lse;
    }
}

// ---------------- host orchestration ----------------
extern "C" void kernel_launch(void* const* d_in, const int* in_sizes, int n_in,
                              void* d_out, int out_size)
{
    const float* features = (const float*)d_in[0];
    const float* Wscalar  = (const float*)d_in[1];
    const float* W_rel    = (const float*)d_in[2];
    const float* W_root   = (const float*)d_in[3];
    const float* b_rgcn   = (const float*)d_in[4];
    const float* W_nbr    = (const float*)d_in[5];
    const float* W_self   = (const float*)d_in[6];
    const float* b_gc     = (const float*)d_in[7];
    const float* W_match  = (const float*)d_in[8];
    const float* b_match  = (const float*)d_in[9];
    const float* W_lin    = (const float*)d_in[10];
    const float* b_lin    = (const float*)d_in[11];
    const float* W_fc     = (const float*)d_in[12];
    const float* b_fc     = (const float*)d_in[13];
    const int*   speakers = (const int*)  d_in[14];
    // d_in[15], d_in[16]: pair_i / pair_k — static banded window; handled analytically.
    float* out = (float*)d_out;

    float *x, *P, *HA, *h1, *nbr, *h2, *em, *XT, *S, *ATT, *HID;
    cudaGetSymbolAddress((void**)&x,   g_x);
    cudaGetSymbolAddress((void**)&P,   g_P);
    cudaGetSymbolAddress((void**)&HA,  g_HA);
    cudaGetSymbolAddress((void**)&h1,  g_h1);
    cudaGetSymbolAddress((void**)&nbr, g_nbr);
    cudaGetSymbolAddress((void**)&h2,  g_h2);
    cudaGetSymbolAddress((void**)&em,  g_em);
    cudaGetSymbolAddress((void**)&XT,  g_XT);
    cudaGetSymbolAddress((void**)&S,   g_S);
    cudaGetSymbolAddress((void**)&ATT, g_ATT);
    cudaGetSymbolAddress((void**)&HID, g_HID);

    // 1. transpose features -> x [N, D]
    make_x_kernel<<<NTOT, 256>>>(features);

    // 2. P = x @ Wscalar  [16384,1024] x [1024,256]
    sgemm<0,false,false,false><<<dim3(LSEQ/128, NTOT/128), 256>>>(
        x, Wscalar, P, nullptr, NTOT, LSEQ, DD, DD, LSEQ, LSEQ, 0, 0, 0);

    // 3. edge softmax -> EW
    edge_softmax_kernel<<<BB * LSEQ, 256>>>();

    // 4. HA = x @ [W_rel(0..7) | W_root]  (9 GEMMs into [N,4608])
    for (int r = 0; r < 9; r++) {
        const float* Bm = (r < 8) ? (W_rel + (long long)r * DD * HH) : W_root;
        sgemm<0,false,false,false><<<dim3(HH/128, NTOT/128), 256>>>(
            x, Bm, HA + r * HH, nullptr, NTOT, HH, DD, DD, HH, HA_COLS, 0, 0, 0);
    }

    // 5. RGCN aggregation -> h1
    rgcn_agg_kernel<<<NTOT, 512>>>(speakers, b_rgcn);

    // 6. GraphConv: sliding neighbor sum, then h2 = nbr@W_nbr + h1@W_self + b_gc
    nbr_kernel<<<dim3(BB, LSEQ/64), 512>>>();
    sgemm<0,false,false,true><<<dim3(HH/128, NTOT/128), 256>>>(
        nbr, W_nbr, h2, b_gc, NTOT, HH, HH, HH, HH, HH, 0, 0, 0);
    sgemm<0,false,true,false><<<dim3(HH/128, NTOT/128), 256>>>(
        h1, W_self, h2, nullptr, NTOT, HH, HH, HH, HH, HH, 0, 0, 0);

    // 7. em = concat(x, h2); XT = em @ W_match + b_match
    build_em_kernel<<<NTOT, 256>>>();
    sgemm<0,false,false,true><<<dim3(DHE/128, NTOT/128), 256>>>(
        em, W_match, XT, b_match, NTOT, DHE, DHE, DHE, DHE, DHE, 0, 0, 0);

    // 8. batched S_b = tanh(XT_b @ em_b^T); softmax rows; ATT_b = S_b @ em_b
    sgemm<2,true,false,false><<<dim3(LSEQ/128, LSEQ/128, BB), 256>>>(
        XT, em, S, nullptr, LSEQ, LSEQ, DHE, DHE, DHE, LSEQ,
        (long long)LSEQ * DHE, (long long)LSEQ * DHE, (long long)LSEQ * LSEQ);
    softmax_rows_kernel<<<BB * LSEQ, 256>>>();
    sgemm<0,false,false,false><<<dim3(DHE/128, LSEQ/128, BB), 256>>>(
        S, em, ATT, nullptr, LSEQ, DHE, LSEQ, LSEQ, DHE, DHE,
        (long long)LSEQ * LSEQ, (long long)LSEQ * DHE, (long long)LSEQ * DHE);

    // 9. HID = relu(ATT @ W_lin + b_lin)
    sgemm<1,false,false,true><<<dim3(HH/128, NTOT/128), 256>>>(
        ATT, W_lin, HID, b_lin, NTOT, HH, DHE, DHE, HH, HH, 0, 0, 0);

    // 10. logits + log_softmax -> out
    final_kernel<<<(NTOT * 32 + 127) / 128, 128>>>(W_fc, b_fc, out);
}

// round 2
// speedup vs baseline: 2.4306x; 2.4306x over previous
#include <cuda_runtime.h>
#include <math.h>
#include <stdint.h>

// Problem constants
#define LSEQ 256
#define BB   64
#define DD   1024
#define HH   512
#define RR   8
#define CC   6
#define NTOT 16384          // B*L
#define DHE  1536           // D + H
#define WINR 10
#define WSZ  21             // 2*WIN+1
#define HA_COLS 4608        // 9 * 512  (8 relations + root)

// ---------------- scratch (device globals; no allocation) ----------------
__device__ float g_x  [(size_t)NTOT * DD];
__device__ float g_P  [(size_t)NTOT * LSEQ];
__device__ float g_EW [(size_t)BB * LSEQ * WSZ];
__device__ float g_HA [(size_t)NTOT * HA_COLS];
__device__ float g_h1 [(size_t)NTOT * HH];
__device__ float g_nbr[(size_t)NTOT * HH];
__device__ float g_h2 [(size_t)NTOT * HH];
__device__ float g_em [(size_t)NTOT * DHE];
__device__ float g_XT [(size_t)NTOT * DHE];
__device__ float g_S  [(size_t)BB * LSEQ * LSEQ];
__device__ float g_ATT[(size_t)NTOT * DHE];
__device__ float g_HID[(size_t)NTOT * HH];

__device__ __forceinline__ float to_tf32(float x) {
    float y;
    asm("cvt.rna.tf32.f32 %0, %1;" : "=f"(y) : "f"(x));
    return y;
}

// ---------------- tf32 tensor-core SGEMM: C = A @ B(^T) ----------------
// 128x128 block tile, BK=16 (double buffered), 256 threads = 8 warps (2m x 4n),
// warp tile 64x32 built from m16n8k8 tf32 MMA atoms, fp32 accumulate.
// Requires M%128==0, N%128==0, K%16==0 (all shapes here satisfy this).
// ACT: 0 none, 1 relu, 2 tanh.  ACC: C += result.  BIAS: add bias[col].
template<int ACT, bool BT, bool ACC, bool BIAS>
__global__ __launch_bounds__(256) void sgemm(
    const float* __restrict__ A, const float* __restrict__ B,
    float* __restrict__ C, const float* __restrict__ bias,
    int M, int N, int K, int lda, int ldb, int ldc,
    long long sA, long long sB, long long sC)
{
    A += (long long)blockIdx.z * sA;
    B += (long long)blockIdx.z * sB;
    C += (long long)blockIdx.z * sC;

    // padded to 136 floats per k-row: fragment loads are bank-conflict free
    __shared__ float As[2][16][136];   // As[k][m]
    __shared__ float Bs[2][16][136];   // Bs[k][n]

    const int tid  = threadIdx.x;
    const int lane = tid & 31;
    const int wid  = tid >> 5;          // 0..7
    const int wm   = wid & 1;           // 2 warps in m
    const int wn   = wid >> 1;          // 4 warps in n
    const int g    = lane >> 2;         // 0..7
    const int t    = lane & 3;          // 0..3

    const int m0 = blockIdx.y * 128;
    const int n0 = blockIdx.x * 128;

    // global load assignments
    const int arow = tid >> 1;          // 0..127
    const int akb  = (tid & 1) * 8;     // k sub-base 0 or 8
    const int bkr  = tid >> 4;          // 0..15  (!BT)
    const int bnc  = (tid & 15) * 8;    // 0..120 (!BT)

    float acc[4][4][4];
    #pragma unroll
    for (int i = 0; i < 4; i++)
        #pragma unroll
        for (int j = 0; j < 4; j++)
            #pragma unroll
            for (int e = 0; e < 4; e++) acc[i][j][e] = 0.f;

    float4 av0, av1, bv0, bv1;

    // prologue: global load of slab 0
    {
        const float* ap = A + (long long)(m0 + arow) * lda + akb;
        av0 = ((const float4*)ap)[0];
        av1 = ((const float4*)ap)[1];
        if (!BT) {
            const float* bp = B + (long long)bkr * ldb + n0 + bnc;
            bv0 = ((const float4*)bp)[0];
            bv1 = ((const float4*)bp)[1];
        } else {
            const float* bp = B + (long long)(n0 + arow) * ldb + akb;
            bv0 = ((const float4*)bp)[0];
            bv1 = ((const float4*)bp)[1];
        }
    }
    // store slab 0 into buffer 0
    {
        As[0][akb+0][arow] = to_tf32(av0.x); As[0][akb+1][arow] = to_tf32(av0.y);
        As[0][akb+2][arow] = to_tf32(av0.z); As[0][akb+3][arow] = to_tf32(av0.w);
        As[0][akb+4][arow] = to_tf32(av1.x); As[0][akb+5][arow] = to_tf32(av1.y);
        As[0][akb+6][arow] = to_tf32(av1.z); As[0][akb+7][arow] = to_tf32(av1.w);
        if (!BT) {
            float4 c0 = make_float4(to_tf32(bv0.x), to_tf32(bv0.y), to_tf32(bv0.z), to_tf32(bv0.w));
            float4 c1 = make_float4(to_tf32(bv1.x), to_tf32(bv1.y), to_tf32(bv1.z), to_tf32(bv1.w));
            *(float4*)&Bs[0][bkr][bnc]     = c0;
            *(float4*)&Bs[0][bkr][bnc + 4] = c1;
        } else {
            Bs[0][akb+0][arow] = to_tf32(bv0.x); Bs[0][akb+1][arow] = to_tf32(bv0.y);
            Bs[0][akb+2][arow] = to_tf32(bv0.z); Bs[0][akb+3][arow] = to_tf32(bv0.w);
            Bs[0][akb+4][arow] = to_tf32(bv1.x); Bs[0][akb+5][arow] = to_tf32(bv1.y);
            Bs[0][akb+6][arow] = to_tf32(bv1.z); Bs[0][akb+7][arow] = to_tf32(bv1.w);
        }
    }
    __syncthreads();

    int cur = 0;
    for (int k0 = 0; k0 < K; k0 += 16) {
        const bool has_next = (k0 + 16) < K;
        if (has_next) {
            const int kn = k0 + 16;
            const float* ap = A + (long long)(m0 + arow) * lda + kn + akb;
            av0 = ((const float4*)ap)[0];
            av1 = ((const float4*)ap)[1];
            if (!BT) {
                const float* bp = B + (long long)(kn + bkr) * ldb + n0 + bnc;
                bv0 = ((const float4*)bp)[0];
                bv1 = ((const float4*)bp)[1];
            } else {
                const float* bp = B + (long long)(n0 + arow) * ldb + kn + akb;
                bv0 = ((const float4*)bp)[0];
                bv1 = ((const float4*)bp)[1];
            }
        }

        // compute on current buffer
        #pragma unroll
        for (int ks = 0; ks < 16; ks += 8) {
            uint32_t af[4][4], bf[4][2];
            #pragma unroll
            for (int mt = 0; mt < 4; mt++) {
                const int rm = wm * 64 + mt * 16;
                af[mt][0] = __float_as_uint(As[cur][ks + t    ][rm + g    ]);
                af[mt][1] = __float_as_uint(As[cur][ks + t    ][rm + g + 8]);
                af[mt][2] = __float_as_uint(As[cur][ks + t + 4][rm + g    ]);
                af[mt][3] = __float_as_uint(As[cur][ks + t + 4][rm + g + 8]);
            }
            #pragma unroll
            for (int nt = 0; nt < 4; nt++) {
                const int cn = wn * 32 + nt * 8;
                bf[nt][0] = __float_as_uint(Bs[cur][ks + t    ][cn + g]);
                bf[nt][1] = __float_as_uint(Bs[cur][ks + t + 4][cn + g]);
            }
            #pragma unroll
            for (int mt = 0; mt < 4; mt++)
                #pragma unroll
                for (int nt = 0; nt < 4; nt++) {
                    asm volatile(
                        "mma.sync.aligned.m16n8k8.row.col.f32.tf32.tf32.f32 "
                        "{%0,%1,%2,%3}, {%4,%5,%6,%7}, {%8,%9}, {%0,%1,%2,%3};"
                        : "+f"(acc[mt][nt][0]), "+f"(acc[mt][nt][1]),
                          "+f"(acc[mt][nt][2]), "+f"(acc[mt][nt][3])
                        : "r"(af[mt][0]), "r"(af[mt][1]), "r"(af[mt][2]), "r"(af[mt][3]),
                          "r"(bf[nt][0]), "r"(bf[nt][1]));
                }
        }

        if (has_next) {
            __syncthreads();  // everyone done reading both buffers up to here
            const int nxt = cur ^ 1;
            As[nxt][akb+0][arow] = to_tf32(av0.x); As[nxt][akb+1][arow] = to_tf32(av0.y);
            As[nxt][akb+2][arow] = to_tf32(av0.z); As[nxt][akb+3][arow] = to_tf32(av0.w);
            As[nxt][akb+4][arow] = to_tf32(av1.x); As[nxt][akb+5][arow] = to_tf32(av1.y);
            As[nxt][akb+6][arow] = to_tf32(av1.z); As[nxt][akb+7][arow] = to_tf32(av1.w);
            if (!BT) {
                float4 c0 = make_float4(to_tf32(bv0.x), to_tf32(bv0.y), to_tf32(bv0.z), to_tf32(bv0.w));
                float4 c1 = make_float4(to_tf32(bv1.x), to_tf32(bv1.y), to_tf32(bv1.z), to_tf32(bv1.w));
                *(float4*)&Bs[nxt][bkr][bnc]     = c0;
                *(float4*)&Bs[nxt][bkr][bnc + 4] = c1;
            } else {
                Bs[nxt][akb+0][arow] = to_tf32(bv0.x); Bs[nxt][akb+1][arow] = to_tf32(bv0.y);
                Bs[nxt][akb+2][arow] = to_tf32(bv0.z); Bs[nxt][akb+3][arow] = to_tf32(bv0.w);
                Bs[nxt][akb+4][arow] = to_tf32(bv1.x); Bs[nxt][akb+5][arow] = to_tf32(bv1.y);
                Bs[nxt][akb+6][arow] = to_tf32(bv1.z); Bs[nxt][akb+7][arow] = to_tf32(bv1.w);
            }
            __syncthreads();
            cur = nxt;
        }
    }

    // epilogue
    #pragma unroll
    for (int mt = 0; mt < 4; mt++) {
        #pragma unroll
        for (int nt = 0; nt < 4; nt++) {
            const int col = n0 + wn * 32 + nt * 8 + t * 2;
            #pragma unroll
            for (int half = 0; half < 2; half++) {
                const long long row = m0 + wm * 64 + mt * 16 + g + half * 8;
                float v0 = acc[mt][nt][half * 2 + 0];
                float v1 = acc[mt][nt][half * 2 + 1];
                float* cp = C + row * ldc + col;
                if (ACC)  { float2 o = *(float2*)cp; v0 += o.x; v1 += o.y; }
                if (BIAS) { v0 += bias[col]; v1 += bias[col + 1]; }
                if (ACT == 1) { v0 = fmaxf(v0, 0.f); v1 = fmaxf(v1, 0.f); }
                if (ACT == 2) { v0 = tanhf(v0); v1 = tanhf(v1); }
                *(float2*)cp = make_float2(v0, v1);
            }
        }
    }
}

// ---------------- stage kernels ----------------

// x[(b*L+s), d] = features[s, b, d]
__global__ void make_x_kernel(const float* __restrict__ f)
{
    const int n = blockIdx.x;               // b*256 + s
    const int b = n >> 8, s = n & 255;
    const float* src = f + ((long long)s * BB + b) * DD;
    float* dst = g_x + (long long)n * DD;
    for (int d = threadIdx.x; d < DD; d += blockDim.x) dst[d] = src[d];
}

// Per (b, anchor i): softmax over s of P[(b,s), i], windowed renorm, emit 21 weights.
__global__ void edge_softmax_kernel()
{
    __shared__ float red[256];
    const int bi = blockIdx.x;              // b*256 + i
    const int b = bi >> 8, i = bi & 255;
    const int s = threadIdx.x;

    const float v = g_P[((long long)(b * 256 + s)) * LSEQ + i];

    red[s] = v; __syncthreads();
    for (int o = 128; o > 0; o >>= 1) { if (s < o) red[s] = fmaxf(red[s], red[s + o]); __syncthreads(); }
    const float m = red[0]; __syncthreads();

    const float e = __expf(v - m);
    red[s] = e; __syncthreads();
    for (int o = 128; o > 0; o >>= 1) { if (s < o) red[s] += red[s + o]; __syncthreads(); }
    const float Z = red[0]; __syncthreads();

    const bool inwin = (s >= i - WINR) && (s <= i + WINR);
    red[s] = inwin ? e : 0.f; __syncthreads();
    for (int o = 128; o > 0; o >>= 1) { if (s < o) red[s] += red[s + o]; __syncthreads(); }
    const float Swin = red[0];

    const float denom = Swin + 1e-10f * (Z - Swin);
    if (inwin)
        g_EW[(long long)bi * WSZ + (s - i + WINR)] = e / denom;
    if (s < WSZ) {
        const int k = i - WINR + s;
        if (k < 0 || k >= LSEQ) g_EW[(long long)bi * WSZ + s] = 0.f;
    }
}

// h1[n=(b,k), h] = HA_root + b_rgcn + sum_{i in win(k)} w(b,i,k) * HA[(b,i), rel, h]
__global__ __launch_bounds__(512) void rgcn_agg_kernel(
    const int* __restrict__ speakers, const float* __restrict__ b_rgcn)
{
    const int n = blockIdx.x;
    const int b = n >> 8, k = n & 255;
    const int h = threadIdx.x;

    __shared__ int   sp[WSZ];
    __shared__ float w [WSZ];
    const int lo = max(k - WINR, 0), hi = min(k + WINR, LSEQ - 1);
    const int cnt = hi - lo + 1;
    if (h < cnt) {
        const int i = lo + h;
        sp[h] = speakers[i * BB + b];
        w [h] = g_EW[((long long)(b * 256 + i)) * WSZ + (k - i + WINR)];
    }
    __syncthreads();

    const int spk = sp[k - lo];            // k is always inside its own window
    float acc = g_HA[(long long)n * HA_COLS + 4096 + h] + b_rgcn[h];
    for (int t = 0; t < cnt; t++) {
        const int i = lo + t;
        const int rel = sp[t] * 4 + spk * 2 + ((i < k) ? 0 : 1);
        acc += w[t] * g_HA[((long long)(b * 256 + i)) * HA_COLS + rel * HH + h];
    }
    g_h1[(long long)n * HH + h] = acc;
}

// Sliding-window neighbor sum: nbr[b,k,h] = sum_{j in [k-10,k+10]} h1[b,j,h]
__global__ __launch_bounds__(512) void nbr_kernel()
{
    const int b = blockIdx.x;
    const int kstart = blockIdx.y * 64;
    const int h = threadIdx.x;

    float run = 0.f;
    const int lo = max(kstart - WINR, 0), hi = min(kstart + WINR, LSEQ - 1);
    for (int j = lo; j <= hi; j++) run += g_h1[((long long)(b * 256 + j)) * HH + h];
    g_nbr[((long long)(b * 256 + kstart)) * HH + h] = run;

    for (int k = kstart + 1; k < kstart + 64; k++) {
        const int add = k + WINR, sub = k - WINR - 1;
        if (add < LSEQ) run += g_h1[((long long)(b * 256 + add)) * HH + h];
        if (sub >= 0)   run -= g_h1[((long long)(b * 256 + sub)) * HH + h];
        g_nbr[((long long)(b * 256 + k)) * HH + h] = run;
    }
}

// em = concat(x, h2)
__global__ void build_em_kernel()
{
    const int n = blockIdx.x;
    float* dst = g_em + (long long)n * DHE;
    const float* xs = g_x + (long long)n * DD;
    const float* hs = g_h2 + (long long)n * HH;
    for (int d = threadIdx.x; d < DD; d += blockDim.x) dst[d] = xs[d];
    for (int d = threadIdx.x; d < HH; d += blockDim.x) dst[DD + d] = hs[d];
}

// Row softmax over contiguous 256-length rows of g_S (already tanh'd)
__global__ void softmax_rows_kernel()
{
    __shared__ float red[256];
    const long long r = blockIdx.x;
    const int s = threadIdx.x;
    const float v = g_S[r * 256 + s];

    red[s] = v; __syncthreads();
    for (int o = 128; o > 0; o >>= 1) { if (s < o) red[s] = fmaxf(red[s], red[s + o]); __syncthreads(); }
    const float m = red[0]; __syncthreads();
    const float e = __expf(v - m);
    red[s] = e; __syncthreads();
    for (int o = 128; o > 0; o >>= 1) { if (s < o) red[s] += red[s + o]; __syncthreads(); }
    g_S[r * 256 + s] = e / red[0];
}

// logits = HID @ W_fc + b_fc ; out = log_softmax(logits).  One warp per node.
__global__ void final_kernel(const float* __restrict__ W_fc,
                             const float* __restrict__ b_fc,
                             float* __restrict__ out)
{
    const int gwarp = (blockIdx.x * blockDim.x + threadIdx.x) >> 5;
    const int lane = threadIdx.x & 31;
    if (gwarp >= NTOT) return;

    float p[CC] = {0.f, 0.f, 0.f, 0.f, 0.f, 0.f};
    #pragma unroll
    for (int j = 0; j < 16; j++) {
        const int hidx = lane + j * 32;
        const float hv = g_HID[(long long)gwarp * HH + hidx];
        const float* wr = W_fc + (long long)hidx * CC;
        #pragma unroll
        for (int c = 0; c < CC; c++) p[c] += hv * wr[c];
    }
    #pragma unroll
    for (int o = 16; o > 0; o >>= 1)
        #pragma unroll
        for (int c = 0; c < CC; c++) p[c] += __shfl_down_sync(0xffffffffu, p[c], o);

    if (lane == 0) {
        float lg[CC], m = -1e30f;
        #pragma unroll
        for (int c = 0; c < CC; c++) { lg[c] = p[c] + b_fc[c]; m = fmaxf(m, lg[c]); }
        float ssum = 0.f;
        #pragma unroll
        for (int c = 0; c < CC; c++) ssum += __expf(lg[c] - m);
        const float lse = m + logf(ssum);
        #pragma unroll
        for (int c = 0; c < CC; c++) out[(long long)gwarp * CC + c] = lg[c] - lse;
    }
}

// ---------------- host orchestration ----------------
extern "C" void kernel_launch(void* const* d_in, const int* in_sizes, int n_in,
                              void* d_out, int out_size)
{
    const float* features = (const float*)d_in[0];
    const float* Wscalar  = (const float*)d_in[1];
    const float* W_rel    = (const float*)d_in[2];
    const float* W_root   = (const float*)d_in[3];
    const float* b_rgcn   = (const float*)d_in[4];
    const float* W_nbr    = (const float*)d_in[5];
    const float* W_self   = (const float*)d_in[6];
    const float* b_gc     = (const float*)d_in[7];
    const float* W_match  = (const float*)d_in[8];
    const float* b_match  = (const float*)d_in[9];
    const float* W_lin    = (const float*)d_in[10];
    const float* b_lin    = (const float*)d_in[11];
    const float* W_fc     = (const float*)d_in[12];
    const float* b_fc     = (const float*)d_in[13];
    const int*   speakers = (const int*)  d_in[14];
    float* out = (float*)d_out;

    float *x, *P, *HA, *h1, *nbr, *h2, *em, *XT, *S, *ATT, *HID;
    cudaGetSymbolAddress((void**)&x,   g_x);
    cudaGetSymbolAddress((void**)&P,   g_P);
    cudaGetSymbolAddress((void**)&HA,  g_HA);
    cudaGetSymbolAddress((void**)&h1,  g_h1);
    cudaGetSymbolAddress((void**)&nbr, g_nbr);
    cudaGetSymbolAddress((void**)&h2,  g_h2);
    cudaGetSymbolAddress((void**)&em,  g_em);
    cudaGetSymbolAddress((void**)&XT,  g_XT);
    cudaGetSymbolAddress((void**)&S,   g_S);
    cudaGetSymbolAddress((void**)&ATT, g_ATT);
    cudaGetSymbolAddress((void**)&HID, g_HID);

    // 1. transpose features -> x [N, D]
    make_x_kernel<<<NTOT, 256>>>(features);

    // 2. P = x @ Wscalar  [16384,1024] x [1024,256]
    sgemm<0,false,false,false><<<dim3(LSEQ/128, NTOT/128), 256>>>(
        x, Wscalar, P, nullptr, NTOT, LSEQ, DD, DD, LSEQ, LSEQ, 0, 0, 0);

    // 3. edge softmax -> EW
    edge_softmax_kernel<<<BB * LSEQ, 256>>>();

    // 4. HA = x @ [W_rel(0..7) | W_root]  (9 GEMMs into [N,4608])
    for (int r = 0; r < 9; r++) {
        const float* Bm = (r < 8) ? (W_rel + (long long)r * DD * HH) : W_root;
        sgemm<0,false,false,false><<<dim3(HH/128, NTOT/128), 256>>>(
            x, Bm, HA + r * HH, nullptr, NTOT, HH, DD, DD, HH, HA_COLS, 0, 0, 0);
    }

    // 5. RGCN aggregation -> h1
    rgcn_agg_kernel<<<NTOT, 512>>>(speakers, b_rgcn);

    // 6. GraphConv: sliding neighbor sum, then h2 = nbr@W_nbr + h1@W_self + b_gc
    nbr_kernel<<<dim3(BB, LSEQ/64), 512>>>();
    sgemm<0,false,false,true><<<dim3(HH/128, NTOT/128), 256>>>(
        nbr, W_nbr, h2, b_gc, NTOT, HH, HH, HH, HH, HH, 0, 0, 0);
    sgemm<0,false,true,false><<<dim3(HH/128, NTOT/128), 256>>>(
        h1, W_self, h2, nullptr, NTOT, HH, HH, HH, HH, HH, 0, 0, 0);

    // 7. em = concat(x, h2); XT = em @ W_match + b_match
    build_em_kernel<<<NTOT, 256>>>();
    sgemm<0,false,false,true><<<dim3(DHE/128, NTOT/128), 256>>>(
        em, W_match, XT, b_match, NTOT, DHE, DHE, DHE, DHE, DHE, 0, 0, 0);

    // 8. batched S_b = tanh(XT_b @ em_b^T); softmax rows; ATT_b = S_b @ em_b
    sgemm<2,true,false,false><<<dim3(LSEQ/128, LSEQ/128, BB), 256>>>(
        XT, em, S, nullptr, LSEQ, LSEQ, DHE, DHE, DHE, LSEQ,
        (long long)LSEQ * DHE, (long long)LSEQ * DHE, (long long)LSEQ * LSEQ);
    softmax_rows_kernel<<<BB * LSEQ, 256>>>();
    sgemm<0,false,false,false><<<dim3(DHE/128, LSEQ/128, BB), 256>>>(
        S, em, ATT, nullptr, LSEQ, DHE, LSEQ, LSEQ, DHE, DHE,
        (long long)LSEQ * LSEQ, (long long)LSEQ * DHE, (long long)LSEQ * DHE);

    // 9. HID = relu(ATT @ W_lin + b_lin)
    sgemm<1,false,false,true><<<dim3(HH/128, NTOT/128), 256>>>(
        ATT, W_lin, HID, b_lin, NTOT, HH, DHE, DHE, HH, HH, 0, 0, 0);

    // 10. logits + log_softmax -> out
    final_kernel<<<(NTOT * 32 + 127) / 128, 128>>>(W_fc, b_fc, out);
}

// round 3
// speedup vs baseline: 3.5701x; 1.4688x over previous
#include <cuda_runtime.h>
#include <math.h>
#include <stdint.h>

// Problem constants
#define LSEQ 256
#define BB   64
#define DD   1024
#define HH   512
#define RR   8
#define CC   6
#define NTOT 16384          // B*L
#define DHE  1536           // D + H
#define WINR 10
#define WSZ  21             // 2*WIN+1
#define HA_COLS 4608        // 9 * 512  (8 relations + root)

// ---------------- scratch (device globals; no allocation) ----------------
__device__ __align__(256) float g_x  [(size_t)NTOT * DD];
__device__ __align__(256) float g_P  [(size_t)NTOT * LSEQ];
__device__ __align__(256) float g_EW [(size_t)BB * LSEQ * WSZ];
__device__ __align__(256) float g_HA [(size_t)NTOT * HA_COLS];
__device__ __align__(256) float g_h1 [(size_t)NTOT * HH];
__device__ __align__(256) float g_nbr[(size_t)NTOT * HH];
__device__ __align__(256) float g_h2 [(size_t)NTOT * HH];
__device__ __align__(256) float g_em [(size_t)NTOT * DHE];
__device__ __align__(256) float g_XT [(size_t)NTOT * DHE];
__device__ __align__(256) float g_S  [(size_t)BB * LSEQ * LSEQ];
__device__ __align__(256) float g_ATT[(size_t)NTOT * DHE];
__device__ __align__(256) float g_HID[(size_t)NTOT * HH];

// ---------------- tf32 tensor-core SGEMM with cp.async pipeline ----------------
// C = A @ B(^T).  128x128 block tile, BK=16, 3-stage cp.async pipeline,
// 256 threads = 8 warps (2m x 4n), warp tile 64x32 from m16n8k8 tf32 atoms.
// SMEM: As[m][k] rows padded to 20 floats (conflict-free scalar frag loads),
//       Bs[k][n] rows padded to 136 (!BT) or Bs[n][k] pad 20 (BT).
// fp32 bits fed raw to MMA (hw truncates to tf32).
// ACT: 0 none, 1 relu, 2 tanh.  ACC: C += result.  BIAS: add bias[col].
#define APITCH 20
#define BPITCH 136
#define STG_FLOATS 2560          // max(128*20, 16*136) per stage
#define SMEM_BYTES (6 * STG_FLOATS * 4)

__device__ __forceinline__ void cp16(uint32_t dst, const float* src) {
    asm volatile("cp.async.cg.shared.global [%0], [%1], 16;" :: "r"(dst), "l"(src));
}

template<int ACT, bool BT, bool ACC, bool BIAS>
__global__ __launch_bounds__(256, 2) void sgemm(
    const float* __restrict__ A, const float* __restrict__ B,
    float* __restrict__ C, const float* __restrict__ bias,
    int M, int N, int K, int lda, int ldb, int ldc,
    long long sA, long long sB, long long sC)
{
    A += (long long)blockIdx.z * sA;
    B += (long long)blockIdx.z * sB;
    C += (long long)blockIdx.z * sC;

    extern __shared__ float sm[];
    float* As = sm;                       // 3 stages of 128*20
    float* Bs = sm + 3 * STG_FLOATS;      // 3 stages of (16*136 | 128*20)
    const uint32_t asb = (uint32_t)__cvta_generic_to_shared(As);
    const uint32_t bsb = (uint32_t)__cvta_generic_to_shared(Bs);

    const int tid  = threadIdx.x;
    const int lane = tid & 31;
    const int wid  = tid >> 5;
    const int wm   = wid & 1;
    const int wn   = wid >> 1;
    const int g    = lane >> 2;
    const int t    = lane & 3;

    const int m0 = blockIdx.y * 128;
    const int n0 = blockIdx.x * 128;

    // fill thread assignments
    const int ar = tid >> 2;              // 0..63 (rows; +64 for 2nd chunk)
    const int ac = (tid & 3) * 4;         // k-col 0/4/8/12
    const int bk = tid >> 5;              // 0..7  (!BT k rows; +8)
    const int bc = (tid & 31) * 4;        // 0..124 (!BT n cols)

    float acc[4][4][4];
    #pragma unroll
    for (int i = 0; i < 4; i++)
        #pragma unroll
        for (int j = 0; j < 4; j++)
            #pragma unroll
            for (int e = 0; e < 4; e++) acc[i][j][e] = 0.f;

    const int KT = K / 16;

    // fill one stage (cp.async issue only; caller commits)
    auto fill = [&](int s, int k0) {
        const uint32_t ab = asb + (uint32_t)(s * STG_FLOATS * 4);
        cp16(ab + (ar * APITCH + ac) * 4,        A + (long long)(m0 + ar) * lda + k0 + ac);
        cp16(ab + ((ar + 64) * APITCH + ac) * 4, A + (long long)(m0 + ar + 64) * lda + k0 + ac);
        const uint32_t bb = bsb + (uint32_t)(s * STG_FLOATS * 4);
        if (!BT) {
            cp16(bb + (bk * BPITCH + bc) * 4,       B + (long long)(k0 + bk) * ldb + n0 + bc);
            cp16(bb + ((bk + 8) * BPITCH + bc) * 4, B + (long long)(k0 + bk + 8) * ldb + n0 + bc);
        } else {
            cp16(bb + (ar * APITCH + ac) * 4,        B + (long long)(n0 + ar) * ldb + k0 + ac);
            cp16(bb + ((ar + 64) * APITCH + ac) * 4, B + (long long)(n0 + ar + 64) * ldb + k0 + ac);
        }
    };

    fill(0, 0);  asm volatile("cp.async.commit_group;");
    fill(1, 16); asm volatile("cp.async.commit_group;");

    for (int kt = 0; kt < KT; kt++) {
        asm volatile("cp.async.wait_group 1;" ::: "memory");
        __syncthreads();

        if (kt + 2 < KT) fill((kt + 2) % 3, (kt + 2) * 16);
        asm volatile("cp.async.commit_group;");

        const float* a = As + (kt % 3) * STG_FLOATS;
        const float* b = Bs + (kt % 3) * STG_FLOATS;

        #pragma unroll
        for (int ks = 0; ks < 16; ks += 8) {
            uint32_t af[4][4], bf[4][2];
            #pragma unroll
            for (int mt = 0; mt < 4; mt++) {
                const int rm = wm * 64 + mt * 16;
                af[mt][0] = __float_as_uint(a[(rm + g)     * APITCH + ks + t]);
                af[mt][1] = __float_as_uint(a[(rm + g + 8) * APITCH + ks + t]);
                af[mt][2] = __float_as_uint(a[(rm + g)     * APITCH + ks + t + 4]);
                af[mt][3] = __float_as_uint(a[(rm + g + 8) * APITCH + ks + t + 4]);
            }
            #pragma unroll
            for (int nt = 0; nt < 4; nt++) {
                const int cn = wn * 32 + nt * 8;
                if (!BT) {
                    bf[nt][0] = __float_as_uint(b[(ks + t)     * BPITCH + cn + g]);
                    bf[nt][1] = __float_as_uint(b[(ks + t + 4) * BPITCH + cn + g]);
                } else {
                    bf[nt][0] = __float_as_uint(b[(cn + g) * APITCH + ks + t]);
                    bf[nt][1] = __float_as_uint(b[(cn + g) * APITCH + ks + t + 4]);
                }
            }
            #pragma unroll
            for (int mt = 0; mt < 4; mt++)
                #pragma unroll
                for (int nt = 0; nt < 4; nt++) {
                    asm volatile(
                        "mma.sync.aligned.m16n8k8.row.col.f32.tf32.tf32.f32 "
                        "{%0,%1,%2,%3}, {%4,%5,%6,%7}, {%8,%9}, {%0,%1,%2,%3};"
                        : "+f"(acc[mt][nt][0]), "+f"(acc[mt][nt][1]),
                          "+f"(acc[mt][nt][2]), "+f"(acc[mt][nt][3])
                        : "r"(af[mt][0]), "r"(af[mt][1]), "r"(af[mt][2]), "r"(af[mt][3]),
                          "r"(bf[nt][0]), "r"(bf[nt][1]));
                }
        }
    }

    // epilogue
    #pragma unroll
    for (int mt = 0; mt < 4; mt++) {
        #pragma unroll
        for (int nt = 0; nt < 4; nt++) {
            const int col = n0 + wn * 32 + nt * 8 + t * 2;
            #pragma unroll
            for (int half = 0; half < 2; half++) {
                const long long row = m0 + wm * 64 + mt * 16 + g + half * 8;
                float v0 = acc[mt][nt][half * 2 + 0];
                float v1 = acc[mt][nt][half * 2 + 1];
                float* cp = C + row * ldc + col;
                if (ACC)  { float2 o = *(float2*)cp; v0 += o.x; v1 += o.y; }
                if (BIAS) { v0 += bias[col]; v1 += bias[col + 1]; }
                if (ACT == 1) { v0 = fmaxf(v0, 0.f); v1 = fmaxf(v1, 0.f); }
                if (ACT == 2) { v0 = tanhf(v0); v1 = tanhf(v1); }
                *(float2*)cp = make_float2(v0, v1);
            }
        }
    }
}

// ---------------- stage kernels ----------------

__global__ void make_x_kernel(const float* __restrict__ f)
{
    const int n = blockIdx.x;               // b*256 + s
    const int b = n >> 8, s = n & 255;
    const float* src = f + ((long long)s * BB + b) * DD;
    float* dst = g_x + (long long)n * DD;
    for (int d = threadIdx.x; d < DD; d += blockDim.x) dst[d] = src[d];
}

__global__ void edge_softmax_kernel()
{
    __shared__ float red[256];
    const int bi = blockIdx.x;              // b*256 + i
    const int b = bi >> 8, i = bi & 255;
    const int s = threadIdx.x;

    const float v = g_P[((long long)(b * 256 + s)) * LSEQ + i];

    red[s] = v; __syncthreads();
    for (int o = 128; o > 0; o >>= 1) { if (s < o) red[s] = fmaxf(red[s], red[s + o]); __syncthreads(); }
    const float m = red[0]; __syncthreads();

    const float e = __expf(v - m);
    red[s] = e; __syncthreads();
    for (int o = 128; o > 0; o >>= 1) { if (s < o) red[s] += red[s + o]; __syncthreads(); }
    const float Z = red[0]; __syncthreads();

    const bool inwin = (s >= i - WINR) && (s <= i + WINR);
    red[s] = inwin ? e : 0.f; __syncthreads();
    for (int o = 128; o > 0; o >>= 1) { if (s < o) red[s] += red[s + o]; __syncthreads(); }
    const float Swin = red[0];

    const float denom = Swin + 1e-10f * (Z - Swin);
    if (inwin)
        g_EW[(long long)bi * WSZ + (s - i + WINR)] = e / denom;
    if (s < WSZ) {
        const int k = i - WINR + s;
        if (k < 0 || k >= LSEQ) g_EW[(long long)bi * WSZ + s] = 0.f;
    }
}

__global__ __launch_bounds__(512) void rgcn_agg_kernel(
    const int* __restrict__ speakers, const float* __restrict__ b_rgcn)
{
    const int n = blockIdx.x;
    const int b = n >> 8, k = n & 255;
    const int h = threadIdx.x;

    __shared__ int   sp[WSZ];
    __shared__ float w [WSZ];
    const int lo = max(k - WINR, 0), hi = min(k + WINR, LSEQ - 1);
    const int cnt = hi - lo + 1;
    if (h < cnt) {
        const int i = lo + h;
        sp[h] = speakers[i * BB + b];
        w [h] = g_EW[((long long)(b * 256 + i)) * WSZ + (k - i + WINR)];
    }
    __syncthreads();

    const int spk = sp[k - lo];
    float acc = g_HA[(long long)n * HA_COLS + 4096 + h] + b_rgcn[h];
    for (int t = 0; t < cnt; t++) {
        const int i = lo + t;
        const int rel = sp[t] * 4 + spk * 2 + ((i < k) ? 0 : 1);
        acc += w[t] * g_HA[((long long)(b * 256 + i)) * HA_COLS + rel * HH + h];
    }
    g_h1[(long long)n * HH + h] = acc;
}

__global__ __launch_bounds__(512) void nbr_kernel()
{
    const int b = blockIdx.x;
    const int kstart = blockIdx.y * 64;
    const int h = threadIdx.x;

    float run = 0.f;
    const int lo = max(kstart - WINR, 0), hi = min(kstart + WINR, LSEQ - 1);
    for (int j = lo; j <= hi; j++) run += g_h1[((long long)(b * 256 + j)) * HH + h];
    g_nbr[((long long)(b * 256 + kstart)) * HH + h] = run;

    for (int k = kstart + 1; k < kstart + 64; k++) {
        const int add = k + WINR, sub = k - WINR - 1;
        if (add < LSEQ) run += g_h1[((long long)(b * 256 + add)) * HH + h];
        if (sub >= 0)   run -= g_h1[((long long)(b * 256 + sub)) * HH + h];
        g_nbr[((long long)(b * 256 + k)) * HH + h] = run;
    }
}

__global__ void build_em_kernel()
{
    const int n = blockIdx.x;
    float* dst = g_em + (long long)n * DHE;
    const float* xs = g_x + (long long)n * DD;
    const float* hs = g_h2 + (long long)n * HH;
    for (int d = threadIdx.x; d < DD; d += blockDim.x) dst[d] = xs[d];
    for (int d = threadIdx.x; d < HH; d += blockDim.x) dst[DD + d] = hs[d];
}

__global__ void softmax_rows_kernel()
{
    __shared__ float red[256];
    const long long r = blockIdx.x;
    const int s = threadIdx.x;
    const float v = g_S[r * 256 + s];

    red[s] = v; __syncthreads();
    for (int o = 128; o > 0; o >>= 1) { if (s < o) red[s] = fmaxf(red[s], red[s + o]); __syncthreads(); }
    const float m = red[0]; __syncthreads();
    const float e = __expf(v - m);
    red[s] = e; __syncthreads();
    for (int o = 128; o > 0; o >>= 1) { if (s < o) red[s] += red[s + o]; __syncthreads(); }
    g_S[r * 256 + s] = e / red[0];
}

__global__ void final_kernel(const float* __restrict__ W_fc,
                             const float* __restrict__ b_fc,
                             float* __restrict__ out)
{
    const int gwarp = (blockIdx.x * blockDim.x + threadIdx.x) >> 5;
    const int lane = threadIdx.x & 31;
    if (gwarp >= NTOT) return;

    float p[CC] = {0.f, 0.f, 0.f, 0.f, 0.f, 0.f};
    #pragma unroll
    for (int j = 0; j < 16; j++) {
        const int hidx = lane + j * 32;
        const float hv = g_HID[(long long)gwarp * HH + hidx];
        const float* wr = W_fc + (long long)hidx * CC;
        #pragma unroll
        for (int c = 0; c < CC; c++) p[c] += hv * wr[c];
    }
    #pragma unroll
    for (int o = 16; o > 0; o >>= 1)
        #pragma unroll
        for (int c = 0; c < CC; c++) p[c] += __shfl_down_sync(0xffffffffu, p[c], o);

    if (lane == 0) {
        float lg[CC], m = -1e30f;
        #pragma unroll
        for (int c = 0; c < CC; c++) { lg[c] = p[c] + b_fc[c]; m = fmaxf(m, lg[c]); }
        float ssum = 0.f;
        #pragma unroll
        for (int c = 0; c < CC; c++) ssum += __expf(lg[c] - m);
        const float lse = m + logf(ssum);
        #pragma unroll
        for (int c = 0; c < CC; c++) out[(long long)gwarp * CC + c] = lg[c] - lse;
    }
}

// ---------------- host orchestration ----------------
extern "C" void kernel_launch(void* const* d_in, const int* in_sizes, int n_in,
                              void* d_out, int out_size)
{
    const float* features = (const float*)d_in[0];
    const float* Wscalar  = (const float*)d_in[1];
    const float* W_rel    = (const float*)d_in[2];
    const float* W_root   = (const float*)d_in[3];
    const float* b_rgcn   = (const float*)d_in[4];
    const float* W_nbr    = (const float*)d_in[5];
    const float* W_self   = (const float*)d_in[6];
    const float* b_gc     = (const float*)d_in[7];
    const float* W_match  = (const float*)d_in[8];
    const float* b_match  = (const float*)d_in[9];
    const float* W_lin    = (const float*)d_in[10];
    const float* b_lin    = (const float*)d_in[11];
    const float* W_fc     = (const float*)d_in[12];
    const float* b_fc     = (const float*)d_in[13];
    const int*   speakers = (const int*)  d_in[14];
    float* out = (float*)d_out;

    float *x, *P, *HA, *h1, *nbr, *h2, *em, *XT, *S, *ATT, *HID;
    cudaGetSymbolAddress((void**)&x,   g_x);
    cudaGetSymbolAddress((void**)&P,   g_P);
    cudaGetSymbolAddress((void**)&HA,  g_HA);
    cudaGetSymbolAddress((void**)&h1,  g_h1);
    cudaGetSymbolAddress((void**)&nbr, g_nbr);
    cudaGetSymbolAddress((void**)&h2,  g_h2);
    cudaGetSymbolAddress((void**)&em,  g_em);
    cudaGetSymbolAddress((void**)&XT,  g_XT);
    cudaGetSymbolAddress((void**)&S,   g_S);
    cudaGetSymbolAddress((void**)&ATT, g_ATT);
    cudaGetSymbolAddress((void**)&HID, g_HID);

    // opt-in to >48KB dynamic smem for every instantiation (idempotent)
    cudaFuncSetAttribute(sgemm<0,false,false,false>, cudaFuncAttributeMaxDynamicSharedMemorySize, SMEM_BYTES);
    cudaFuncSetAttribute(sgemm<0,false,false,true>,  cudaFuncAttributeMaxDynamicSharedMemorySize, SMEM_BYTES);
    cudaFuncSetAttribute(sgemm<0,false,true,false>,  cudaFuncAttributeMaxDynamicSharedMemorySize, SMEM_BYTES);
    cudaFuncSetAttribute(sgemm<2,true,false,false>,  cudaFuncAttributeMaxDynamicSharedMemorySize, SMEM_BYTES);
    cudaFuncSetAttribute(sgemm<1,false,false,true>,  cudaFuncAttributeMaxDynamicSharedMemorySize, SMEM_BYTES);

    // 1. transpose features -> x [N, D]
    make_x_kernel<<<NTOT, 256>>>(features);

    // 2. P = x @ Wscalar  [16384,1024] x [1024,256]
    sgemm<0,false,false,false><<<dim3(LSEQ/128, NTOT/128), 256, SMEM_BYTES>>>(
        x, Wscalar, P, nullptr, NTOT, LSEQ, DD, DD, LSEQ, LSEQ, 0, 0, 0);

    // 3. edge softmax -> EW
    edge_softmax_kernel<<<BB * LSEQ, 256>>>();

    // 4. HA = x @ [W_rel(0..7) | W_root]  (z-batched over 8 relations + root)
    sgemm<0,false,false,false><<<dim3(HH/128, NTOT/128, 8), 256, SMEM_BYTES>>>(
        x, W_rel, HA, nullptr, NTOT, HH, DD, DD, HH, HA_COLS,
        0, (long long)DD * HH, (long long)HH);
    sgemm<0,false,false,false><<<dim3(HH/128, NTOT/128), 256, SMEM_BYTES>>>(
        x, W_root, HA + 8 * HH, nullptr, NTOT, HH, DD, DD, HH, HA_COLS, 0, 0, 0);

    // 5. RGCN aggregation -> h1
    rgcn_agg_kernel<<<NTOT, 512>>>(speakers, b_rgcn);

    // 6. GraphConv: sliding neighbor sum, then h2 = nbr@W_nbr + h1@W_self + b_gc
    nbr_kernel<<<dim3(BB, LSEQ/64), 512>>>();
    sgemm<0,false,false,true><<<dim3(HH/128, NTOT/128), 256, SMEM_BYTES>>>(
        nbr, W_nbr, h2, b_gc, NTOT, HH, HH, HH, HH, HH, 0, 0, 0);
    sgemm<0,false,true,false><<<dim3(HH/128, NTOT/128), 256, SMEM_BYTES>>>(
        h1, W_self, h2, nullptr, NTOT, HH, HH, HH, HH, HH, 0, 0, 0);

    // 7. em = concat(x, h2); XT = em @ W_match + b_match
    build_em_kernel<<<NTOT, 256>>>();
    sgemm<0,false,false,true><<<dim3(DHE/128, NTOT/128), 256, SMEM_BYTES>>>(
        em, W_match, XT, b_match, NTOT, DHE, DHE, DHE, DHE, DHE, 0, 0, 0);

    // 8. batched S_b = tanh(XT_b @ em_b^T); softmax rows; ATT_b = S_b @ em_b
    sgemm<2,true,false,false><<<dim3(LSEQ/128, LSEQ/128, BB), 256, SMEM_BYTES>>>(
        XT, em, S, nullptr, LSEQ, LSEQ, DHE, DHE, DHE, LSEQ,
        (long long)LSEQ * DHE, (long long)LSEQ * DHE, (long long)LSEQ * LSEQ);
    softmax_rows_kernel<<<BB * LSEQ, 256>>>();
    sgemm<0,false,false,false><<<dim3(DHE/128, LSEQ/128, BB), 256, SMEM_BYTES>>>(
        S, em, ATT, nullptr, LSEQ, DHE, LSEQ, LSEQ, DHE, DHE,
        (long long)LSEQ * LSEQ, (long long)LSEQ * DHE, (long long)LSEQ * DHE);

    // 9. HID = relu(ATT @ W_lin + b_lin)
    sgemm<1,false,false,true><<<dim3(HH/128, NTOT/128), 256, SMEM_BYTES>>>(
        ATT, W_lin, HID, b_lin, NTOT, HH, DHE, DHE, HH, HH, 0, 0, 0);

    // 10. logits + log_softmax -> out
    final_kernel<<<(NTOT * 32 + 127) / 128, 128>>>(W_fc, b_fc, out);
}

// round 4
// speedup vs baseline: 4.2733x; 1.1970x over previous
#include <cuda_runtime.h>
#include <math.h>
#include <stdint.h>

// Problem constants
#define LSEQ 256
#define BB   64
#define DD   1024
#define HH   512
#define CC   6
#define NTOT 16384          // B*L
#define DHE  1536           // D + H
#define WINR 10
#define WSZ  21             // 2*WIN+1
#define HA4_COLS 2048       // 4 local relation slots * 512
#define MTILES 129          // max m-tiles after per-speaker padding

// ---------------- scratch (device globals; no allocation) ----------------
__device__ __align__(256) float g_x  [(size_t)NTOT * DD];
__device__ __align__(256) float g_P  [(size_t)NTOT * LSEQ];
__device__ __align__(256) float g_EW [(size_t)BB * LSEQ * WSZ];
__device__ __align__(256) float g_HA4[(size_t)NTOT * HA4_COLS];
__device__ __align__(256) float g_h1 [(size_t)NTOT * HH];
__device__ __align__(256) float g_nbr[(size_t)NTOT * HH];
__device__ __align__(256) float g_h2 [(size_t)NTOT * HH];
__device__ __align__(256) float g_em [(size_t)NTOT * DHE];
__device__ __align__(256) float g_XT [(size_t)NTOT * DHE];
__device__ __align__(256) float g_S  [(size_t)BB * LSEQ * LSEQ];
__device__ __align__(256) float g_ATT[(size_t)NTOT * DHE];
__device__ __align__(256) float g_HID[(size_t)NTOT * HH];

// speaker partition state
__device__ int g_cnt[2];
__device__ int g_cnt2[2];
__device__ int g_meta[4];        // M0, M0pad, M1, M1pad
__device__ int g_idx[MTILES * 128];

// ---------------- tf32 tensor-core SGEMM with cp.async pipeline ----------------
// 128x128 block tile, BK=16, 4-stage cp.async pipeline, 256 thr = 8 warps (2m x 4n),
// warp tile 64x32 from m16n8k8 tf32 atoms. fp32 bits fed raw (hw truncates to tf32).
#define APITCH 20
#define BPITCH 136
#define STG_FLOATS 2560          // max(128*20, 16*136)
#define NSTAGE 4
#define SMEM_BYTES (2 * NSTAGE * STG_FLOATS * 4)

__device__ __forceinline__ void cp16(uint32_t dst, const float* src) {
    asm volatile("cp.async.cg.shared.global [%0], [%1], 16;" :: "r"(dst), "l"(src));
}

// shared mainloop compute on one BK=16 slab
__device__ __forceinline__ void slab_mma(
    const float* a, const float* b, bool b_kmajor,
    int wm, int wn, int g, int t, float acc[4][4][4])
{
    #pragma unroll
    for (int ks = 0; ks < 16; ks += 8) {
        uint32_t af[4][4], bf[4][2];
        #pragma unroll
        for (int mt = 0; mt < 4; mt++) {
            const int rm = wm * 64 + mt * 16;
            af[mt][0] = __float_as_uint(a[(rm + g)     * APITCH + ks + t]);
            af[mt][1] = __float_as_uint(a[(rm + g + 8) * APITCH + ks + t]);
            af[mt][2] = __float_as_uint(a[(rm + g)     * APITCH + ks + t + 4]);
            af[mt][3] = __float_as_uint(a[(rm + g + 8) * APITCH + ks + t + 4]);
        }
        #pragma unroll
        for (int nt = 0; nt < 4; nt++) {
            const int cn = wn * 32 + nt * 8;
            if (b_kmajor) {
                bf[nt][0] = __float_as_uint(b[(ks + t)     * BPITCH + cn + g]);
                bf[nt][1] = __float_as_uint(b[(ks + t + 4) * BPITCH + cn + g]);
            } else {
                bf[nt][0] = __float_as_uint(b[(cn + g) * APITCH + ks + t]);
                bf[nt][1] = __float_as_uint(b[(cn + g) * APITCH + ks + t + 4]);
            }
        }
        #pragma unroll
        for (int mt = 0; mt < 4; mt++)
            #pragma unroll
            for (int nt = 0; nt < 4; nt++) {
                asm volatile(
                    "mma.sync.aligned.m16n8k8.row.col.f32.tf32.tf32.f32 "
                    "{%0,%1,%2,%3}, {%4,%5,%6,%7}, {%8,%9}, {%0,%1,%2,%3};"
                    : "+f"(acc[mt][nt][0]), "+f"(acc[mt][nt][1]),
                      "+f"(acc[mt][nt][2]), "+f"(acc[mt][nt][3])
                    : "r"(af[mt][0]), "r"(af[mt][1]), "r"(af[mt][2]), "r"(af[mt][3]),
                      "r"(bf[nt][0]), "r"(bf[nt][1]));
            }
    }
}

template<int ACT, bool BT, bool ACC, bool BIAS>
__global__ __launch_bounds__(256, 2) void sgemm(
    const float* __restrict__ A, const float* __restrict__ B,
    float* __restrict__ C, const float* __restrict__ bias,
    int M, int N, int K, int lda, int ldb, int ldc,
    long long sA, long long sB, long long sC)
{
    A += (long long)blockIdx.z * sA;
    B += (long long)blockIdx.z * sB;
    C += (long long)blockIdx.z * sC;

    extern __shared__ float sm[];
    float* As = sm;
    float* Bs = sm + NSTAGE * STG_FLOATS;
    const uint32_t asb = (uint32_t)__cvta_generic_to_shared(As);
    const uint32_t bsb = (uint32_t)__cvta_generic_to_shared(Bs);

    const int tid  = threadIdx.x;
    const int lane = tid & 31;
    const int wid  = tid >> 5;
    const int wm   = wid & 1;
    const int wn   = wid >> 1;
    const int g    = lane >> 2;
    const int t    = lane & 3;

    const int m0 = blockIdx.y * 128;
    const int n0 = blockIdx.x * 128;

    const int ar = tid >> 2;
    const int ac = (tid & 3) * 4;
    const int bk = tid >> 5;
    const int bc = (tid & 31) * 4;

    float acc[4][4][4];
    #pragma unroll
    for (int i = 0; i < 4; i++)
        #pragma unroll
        for (int j = 0; j < 4; j++)
            #pragma unroll
            for (int e = 0; e < 4; e++) acc[i][j][e] = 0.f;

    const int KT = K / 16;

    auto fill = [&](int s, int k0) {
        const uint32_t ab = asb + (uint32_t)(s * STG_FLOATS * 4);
        cp16(ab + (ar * APITCH + ac) * 4,        A + (long long)(m0 + ar) * lda + k0 + ac);
        cp16(ab + ((ar + 64) * APITCH + ac) * 4, A + (long long)(m0 + ar + 64) * lda + k0 + ac);
        const uint32_t bb = bsb + (uint32_t)(s * STG_FLOATS * 4);
        if (!BT) {
            cp16(bb + (bk * BPITCH + bc) * 4,       B + (long long)(k0 + bk) * ldb + n0 + bc);
            cp16(bb + ((bk + 8) * BPITCH + bc) * 4, B + (long long)(k0 + bk + 8) * ldb + n0 + bc);
        } else {
            cp16(bb + (ar * APITCH + ac) * 4,        B + (long long)(n0 + ar) * ldb + k0 + ac);
            cp16(bb + ((ar + 64) * APITCH + ac) * 4, B + (long long)(n0 + ar + 64) * ldb + k0 + ac);
        }
    };

    fill(0, 0);  asm volatile("cp.async.commit_group;");
    fill(1, 16); asm volatile("cp.async.commit_group;");
    fill(2, 32); asm volatile("cp.async.commit_group;");

    for (int kt = 0; kt < KT; kt++) {
        asm volatile("cp.async.wait_group 2;" ::: "memory");
        __syncthreads();
        if (kt + 3 < KT) fill((kt + 3) & 3, (kt + 3) * 16);
        asm volatile("cp.async.commit_group;");

        slab_mma(As + (kt & 3) * STG_FLOATS, Bs + (kt & 3) * STG_FLOATS, !BT,
                 wm, wn, g, t, acc);
    }

    #pragma unroll
    for (int mt = 0; mt < 4; mt++) {
        #pragma unroll
        for (int nt = 0; nt < 4; nt++) {
            const int col = n0 + wn * 32 + nt * 8 + t * 2;
            #pragma unroll
            for (int half = 0; half < 2; half++) {
                const long long row = m0 + wm * 64 + mt * 16 + g + half * 8;
                float v0 = acc[mt][nt][half * 2 + 0];
                float v1 = acc[mt][nt][half * 2 + 1];
                float* cp = C + row * ldc + col;
                if (ACC)  { float2 o = *(float2*)cp; v0 += o.x; v1 += o.y; }
                if (BIAS) { v0 += bias[col]; v1 += bias[col + 1]; }
                if (ACT == 1) { v0 = fmaxf(v0, 0.f); v1 = fmaxf(v1, 0.f); }
                if (ACT == 2) { v0 = tanhf(v0); v1 = tanhf(v1); }
                *(float2*)cp = make_float2(v0, v1);
            }
        }
    }
}

// ---------------- speaker-split relation GEMM ----------------
// HA4[node, j*512 + h] = sum_d x[node,d] * W_rel[sp(node)*4 + j][d,h]
// grid: (4 n-tiles, 129 m-tiles, 4 j)
__global__ __launch_bounds__(256, 2) void rel_gemm(const float* __restrict__ W_rel)
{
    const int M0    = g_meta[0];
    const int M0pad = g_meta[1];
    const int M1    = g_meta[2];
    const int M1pad = g_meta[3];

    const int m0 = blockIdx.y * 128;
    if (m0 >= M0pad + M1pad) return;
    const int grp = (m0 < M0pad) ? 0 : 1;

    extern __shared__ float sm[];
    float* As = sm;
    float* Bs = sm + NSTAGE * STG_FLOATS;
    __shared__ int sidx[128];
    const uint32_t asb = (uint32_t)__cvta_generic_to_shared(As);
    const uint32_t bsb = (uint32_t)__cvta_generic_to_shared(Bs);

    const int tid  = threadIdx.x;
    const int lane = tid & 31;
    const int wid  = tid >> 5;
    const int wm   = wid & 1;
    const int wn   = wid >> 1;
    const int g    = lane >> 2;
    const int t    = lane & 3;
    const int n0   = blockIdx.x * 128;
    const int j    = blockIdx.z;

    const float* B = W_rel + (long long)(grp * 4 + j) * DD * HH;

    if (tid < 128) sidx[tid] = g_idx[m0 + tid];

    const int ar = tid >> 2;
    const int ac = (tid & 3) * 4;
    const int bk = tid >> 5;
    const int bc = (tid & 31) * 4;
    const long long iA0 = g_idx[m0 + ar];
    const long long iA1 = g_idx[m0 + ar + 64];

    float acc[4][4][4];
    #pragma unroll
    for (int i = 0; i < 4; i++)
        #pragma unroll
        for (int jj = 0; jj < 4; jj++)
            #pragma unroll
            for (int e = 0; e < 4; e++) acc[i][jj][e] = 0.f;

    const int KT = DD / 16;

    auto fill = [&](int s, int k0) {
        const uint32_t ab = asb + (uint32_t)(s * STG_FLOATS * 4);
        cp16(ab + (ar * APITCH + ac) * 4,        g_x + iA0 * DD + k0 + ac);
        cp16(ab + ((ar + 64) * APITCH + ac) * 4, g_x + iA1 * DD + k0 + ac);
        const uint32_t bb = bsb + (uint32_t)(s * STG_FLOATS * 4);
        cp16(bb + (bk * BPITCH + bc) * 4,       B + (long long)(k0 + bk) * HH + n0 + bc);
        cp16(bb + ((bk + 8) * BPITCH + bc) * 4, B + (long long)(k0 + bk + 8) * HH + n0 + bc);
    };

    fill(0, 0);  asm volatile("cp.async.commit_group;");
    fill(1, 16); asm volatile("cp.async.commit_group;");
    fill(2, 32); asm volatile("cp.async.commit_group;");

    for (int kt = 0; kt < KT; kt++) {
        asm volatile("cp.async.wait_group 2;" ::: "memory");
        __syncthreads();
        if (kt + 3 < KT) fill((kt + 3) & 3, (kt + 3) * 16);
        asm volatile("cp.async.commit_group;");
        slab_mma(As + (kt & 3) * STG_FLOATS, Bs + (kt & 3) * STG_FLOATS, true,
                 wm, wn, g, t, acc);
    }

    // scatter epilogue with validity predicate
    #pragma unroll
    for (int mt = 0; mt < 4; mt++) {
        #pragma unroll
        for (int nt = 0; nt < 4; nt++) {
            const int col = j * HH + n0 + wn * 32 + nt * 8 + t * 2;
            #pragma unroll
            for (int half = 0; half < 2; half++) {
                const int lr = wm * 64 + mt * 16 + g + half * 8;   // 0..127
                const int pr = m0 + lr;
                const bool valid = grp == 0 ? (pr < M0) : (pr - M0pad < M1);
                if (valid) {
                    const long long node = sidx[lr];
                    *(float2*)(g_HA4 + node * HA4_COLS + col) =
                        make_float2(acc[mt][nt][half * 2], acc[mt][nt][half * 2 + 1]);
                }
            }
        }
    }
}

// ---------------- partition kernels ----------------
__global__ void part_count(const int* __restrict__ speakers)
{
    const int n = blockIdx.x * blockDim.x + threadIdx.x;
    if (n < MTILES * 128) g_idx[n] = 0;
    if (n < NTOT) {
        const int b = n >> 8, k = n & 255;
        atomicAdd(&g_cnt[speakers[k * BB + b]], 1);
    }
}
__global__ void part_meta()
{
    const int M0 = g_cnt[0], M1 = g_cnt[1];
    g_meta[0] = M0; g_meta[1] = ((M0 + 127) / 128) * 128;
    g_meta[2] = M1; g_meta[3] = ((M1 + 127) / 128) * 128;
    g_cnt[0] = 0; g_cnt[1] = 0;
    g_cnt2[0] = 0; g_cnt2[1] = 0;
}
__global__ void part_assign(const int* __restrict__ speakers)
{
    const int n = blockIdx.x * blockDim.x + threadIdx.x;
    if (n >= NTOT) return;
    const int b = n >> 8, k = n & 255;
    const int sp = speakers[k * BB + b];
    const int slot = atomicAdd(&g_cnt2[sp], 1);
    const int row = (sp == 0) ? slot : g_meta[1] + slot;
    g_idx[row] = n;
}

// ---------------- stage kernels ----------------
__global__ void make_x_kernel(const float* __restrict__ f)
{
    const int n = blockIdx.x;
    const int b = n >> 8, s = n & 255;
    const float* src = f + ((long long)s * BB + b) * DD;
    float* dst = g_x + (long long)n * DD;
    for (int d = threadIdx.x; d < DD; d += blockDim.x) dst[d] = src[d];
}

__global__ void edge_softmax_kernel()
{
    __shared__ float red[256];
    const int bi = blockIdx.x;
    const int b = bi >> 8, i = bi & 255;
    const int s = threadIdx.x;

    const float v = g_P[((long long)(b * 256 + s)) * LSEQ + i];

    red[s] = v; __syncthreads();
    for (int o = 128; o > 0; o >>= 1) { if (s < o) red[s] = fmaxf(red[s], red[s + o]); __syncthreads(); }
    const float m = red[0]; __syncthreads();

    const float e = __expf(v - m);
    red[s] = e; __syncthreads();
    for (int o = 128; o > 0; o >>= 1) { if (s < o) red[s] += red[s + o]; __syncthreads(); }
    const float Z = red[0]; __syncthreads();

    const bool inwin = (s >= i - WINR) && (s <= i + WINR);
    red[s] = inwin ? e : 0.f; __syncthreads();
    for (int o = 128; o > 0; o >>= 1) { if (s < o) red[s] += red[s + o]; __syncthreads(); }
    const float Swin = red[0];

    const float denom = Swin + 1e-10f * (Z - Swin);
    if (inwin)
        g_EW[(long long)bi * WSZ + (s - i + WINR)] = e / denom;
    if (s < WSZ) {
        const int k = i - WINR + s;
        if (k < 0 || k >= LSEQ) g_EW[(long long)bi * WSZ + s] = 0.f;
    }
}

// h1[n=(b,k), h] += sum_{i in win(k)} w(b,i,k) * HA4[(b,i), (sp_k*2+dir)*512 + h]
__global__ __launch_bounds__(512) void rgcn_agg_kernel(const int* __restrict__ speakers)
{
    const int n = blockIdx.x;
    const int b = n >> 8, k = n & 255;
    const int h = threadIdx.x;

    __shared__ float w[WSZ];
    const int lo = max(k - WINR, 0), hi = min(k + WINR, LSEQ - 1);
    const int cnt = hi - lo + 1;
    if (h < cnt) {
        const int i = lo + h;
        w[h] = g_EW[((long long)(b * 256 + i)) * WSZ + (k - i + WINR)];
    }
    __syncthreads();

    const int spk = speakers[k * BB + b];
    float acc = g_h1[(long long)n * HH + h];
    for (int t = 0; t < cnt; t++) {
        const int i = lo + t;
        const int j = spk * 2 + ((i < k) ? 0 : 1);
        acc += w[t] * g_HA4[((long long)(b * 256 + i)) * HA4_COLS + j * HH + h];
    }
    g_h1[(long long)n * HH + h] = acc;
}

__global__ __launch_bounds__(512) void nbr_kernel()
{
    const int b = blockIdx.x;
    const int kstart = blockIdx.y * 64;
    const int h = threadIdx.x;

    float run = 0.f;
    const int lo = max(kstart - WINR, 0), hi = min(kstart + WINR, LSEQ - 1);
    for (int j = lo; j <= hi; j++) run += g_h1[((long long)(b * 256 + j)) * HH + h];
    g_nbr[((long long)(b * 256 + kstart)) * HH + h] = run;

    for (int k = kstart + 1; k < kstart + 64; k++) {
        const int add = k + WINR, sub = k - WINR - 1;
        if (add < LSEQ) run += g_h1[((long long)(b * 256 + add)) * HH + h];
        if (sub >= 0)   run -= g_h1[((long long)(b * 256 + sub)) * HH + h];
        g_nbr[((long long)(b * 256 + k)) * HH + h] = run;
    }
}

__global__ void build_em_kernel()
{
    const int n = blockIdx.x;
    float* dst = g_em + (long long)n * DHE;
    const float* xs = g_x + (long long)n * DD;
    const float* hs = g_h2 + (long long)n * HH;
    for (int d = threadIdx.x; d < DD; d += blockDim.x) dst[d] = xs[d];
    for (int d = threadIdx.x; d < HH; d += blockDim.x) dst[DD + d] = hs[d];
}

__global__ void softmax_rows_kernel()
{
    __shared__ float red[256];
    const long long r = blockIdx.x;
    const int s = threadIdx.x;
    const float v = g_S[r * 256 + s];

    red[s] = v; __syncthreads();
    for (int o = 128; o > 0; o >>= 1) { if (s < o) red[s] = fmaxf(red[s], red[s + o]); __syncthreads(); }
    const float m = red[0]; __syncthreads();
    const float e = __expf(v - m);
    red[s] = e; __syncthreads();
    for (int o = 128; o > 0; o >>= 1) { if (s < o) red[s] += red[s + o]; __syncthreads(); }
    g_S[r * 256 + s] = e / red[0];
}

__global__ void final_kernel(const float* __restrict__ W_fc,
                             const float* __restrict__ b_fc,
                             float* __restrict__ out)
{
    const int gwarp = (blockIdx.x * blockDim.x + threadIdx.x) >> 5;
    const int lane = threadIdx.x & 31;
    if (gwarp >= NTOT) return;

    float p[CC] = {0.f, 0.f, 0.f, 0.f, 0.f, 0.f};
    #pragma unroll
    for (int j = 0; j < 16; j++) {
        const int hidx = lane + j * 32;
        const float hv = g_HID[(long long)gwarp * HH + hidx];
        const float* wr = W_fc + (long long)hidx * CC;
        #pragma unroll
        for (int c = 0; c < CC; c++) p[c] += hv * wr[c];
    }
    #pragma unroll
    for (int o = 16; o > 0; o >>= 1)
        #pragma unroll
        for (int c = 0; c < CC; c++) p[c] += __shfl_down_sync(0xffffffffu, p[c], o);

    if (lane == 0) {
        float lg[CC], m = -1e30f;
        #pragma unroll
        for (int c = 0; c < CC; c++) { lg[c] = p[c] + b_fc[c]; m = fmaxf(m, lg[c]); }
        float ssum = 0.f;
        #pragma unroll
        for (int c = 0; c < CC; c++) ssum += __expf(lg[c] - m);
        const float lse = m + logf(ssum);
        #pragma unroll
        for (int c = 0; c < CC; c++) out[(long long)gwarp * CC + c] = lg[c] - lse;
    }
}

// ---------------- host orchestration ----------------
extern "C" void kernel_launch(void* const* d_in, const int* in_sizes, int n_in,
                              void* d_out, int out_size)
{
    const float* features = (const float*)d_in[0];
    const float* Wscalar  = (const float*)d_in[1];
    const float* W_rel    = (const float*)d_in[2];
    const float* W_root   = (const float*)d_in[3];
    const float* b_rgcn   = (const float*)d_in[4];
    const float* W_nbr    = (const float*)d_in[5];
    const float* W_self   = (const float*)d_in[6];
    const float* b_gc     = (const float*)d_in[7];
    const float* W_match  = (const float*)d_in[8];
    const float* b_match  = (const float*)d_in[9];
    const float* W_lin    = (const float*)d_in[10];
    const float* b_lin    = (const float*)d_in[11];
    const float* W_fc     = (const float*)d_in[12];
    const float* b_fc     = (const float*)d_in[13];
    const int*   speakers = (const int*)  d_in[14];
    float* out = (float*)d_out;

    float *x, *P, *h1, *nbr, *h2, *em, *XT, *S, *ATT, *HID;
    cudaGetSymbolAddress((void**)&x,   g_x);
    cudaGetSymbolAddress((void**)&P,   g_P);
    cudaGetSymbolAddress((void**)&h1,  g_h1);
    cudaGetSymbolAddress((void**)&nbr, g_nbr);
    cudaGetSymbolAddress((void**)&h2,  g_h2);
    cudaGetSymbolAddress((void**)&em,  g_em);
    cudaGetSymbolAddress((void**)&XT,  g_XT);
    cudaGetSymbolAddress((void**)&S,   g_S);
    cudaGetSymbolAddress((void**)&ATT, g_ATT);
    cudaGetSymbolAddress((void**)&HID, g_HID);

    cudaFuncSetAttribute(sgemm<0,false,false,false>, cudaFuncAttributeMaxDynamicSharedMemorySize, SMEM_BYTES);
    cudaFuncSetAttribute(sgemm<0,false,false,true>,  cudaFuncAttributeMaxDynamicSharedMemorySize, SMEM_BYTES);
    cudaFuncSetAttribute(sgemm<0,false,true,false>,  cudaFuncAttributeMaxDynamicSharedMemorySize, SMEM_BYTES);
    cudaFuncSetAttribute(sgemm<2,true,false,false>,  cudaFuncAttributeMaxDynamicSharedMemorySize, SMEM_BYTES);
    cudaFuncSetAttribute(sgemm<1,false,false,true>,  cudaFuncAttributeMaxDynamicSharedMemorySize, SMEM_BYTES);
    cudaFuncSetAttribute(rel_gemm, cudaFuncAttributeMaxDynamicSharedMemorySize, SMEM_BYTES);

    // 1. transpose features -> x; speaker partition
    make_x_kernel<<<NTOT, 256>>>(features);
    part_count<<<(MTILES * 128 + 255) / 256, 256>>>(speakers);
    part_meta<<<1, 1>>>();
    part_assign<<<(NTOT + 255) / 256, 256>>>(speakers);

    // 2. P = x @ Wscalar
    sgemm<0,false,false,false><<<dim3(LSEQ/128, NTOT/128), 256, SMEM_BYTES>>>(
        x, Wscalar, P, nullptr, NTOT, LSEQ, DD, DD, LSEQ, LSEQ, 0, 0, 0);

    // 3. edge softmax -> EW
    edge_softmax_kernel<<<BB * LSEQ, 256>>>();

    // 4. h1 = x @ W_root + b_rgcn ; HA4 = speaker-split relation transforms
    sgemm<0,false,false,true><<<dim3(HH/128, NTOT/128), 256, SMEM_BYTES>>>(
        x, W_root, h1, b_rgcn, NTOT, HH, DD, DD, HH, HH, 0, 0, 0);
    rel_gemm<<<dim3(HH/128, MTILES, 4), 256, SMEM_BYTES>>>(W_rel);

    // 5. RGCN aggregation accumulates into h1
    rgcn_agg_kernel<<<NTOT, 512>>>(speakers);

    // 6. GraphConv
    nbr_kernel<<<dim3(BB, LSEQ/64), 512>>>();
    sgemm<0,false,false,true><<<dim3(HH/128, NTOT/128), 256, SMEM_BYTES>>>(
        nbr, W_nbr, h2, b_gc, NTOT, HH, HH, HH, HH, HH, 0, 0, 0);
    sgemm<0,false,true,false><<<dim3(HH/128, NTOT/128), 256, SMEM_BYTES>>>(
        h1, W_self, h2, nullptr, NTOT, HH, HH, HH, HH, HH, 0, 0, 0);

    // 7. em = concat(x, h2); XT = em @ W_match + b_match
    build_em_kernel<<<NTOT, 256>>>();
    sgemm<0,false,false,true><<<dim3(DHE/128, NTOT/128), 256, SMEM_BYTES>>>(
        em, W_match, XT, b_match, NTOT, DHE, DHE, DHE, DHE, DHE, 0, 0, 0);

    // 8. S = tanh(XT @ em^T) batched; softmax; ATT = S @ em
    sgemm<2,true,false,false><<<dim3(LSEQ/128, LSEQ/128, BB), 256, SMEM_BYTES>>>(
        XT, em, S, nullptr, LSEQ, LSEQ, DHE, DHE, DHE, LSEQ,
        (long long)LSEQ * DHE, (long long)LSEQ * DHE, (long long)LSEQ * LSEQ);
    softmax_rows_kernel<<<BB * LSEQ, 256>>>();
    sgemm<0,false,false,false><<<dim3(DHE/128, LSEQ/128, BB), 256, SMEM_BYTES>>>(
        S, em, ATT, nullptr, LSEQ, DHE, LSEQ, LSEQ, DHE, DHE,
        (long long)LSEQ * LSEQ, (long long)LSEQ * DHE, (long long)LSEQ * DHE);

    // 9. HID = relu(ATT @ W_lin + b_lin)
    sgemm<1,false,false,true><<<dim3(HH/128, NTOT/128), 256, SMEM_BYTES>>>(
        ATT, W_lin, HID, b_lin, NTOT, HH, DHE, DHE, HH, HH, 0, 0, 0);

    // 10. logits + log_softmax -> out
    final_kernel<<<(NTOT * 32 + 127) / 128, 128>>>(W_fc, b_fc, out);
}

// round 6
// speedup vs baseline: 4.4494x; 1.0412x over previous
#include <cuda_runtime.h>
#include <math.h>
#include <stdint.h>

// Problem constants
#define LSEQ 256
#define BB   64
#define DD   1024
#define HH   512
#define CC   6
#define NTOT 16384          // B*L
#define DHE  1536           // D + H
#define WINR 10
#define WSZ  21
#define HA4_COLS 2048       // 4 local relation slots * 512
#define MTILES 129
#define CATK 1024           // [nbr | h1] fused K

// ---------------- scratch (device globals; no allocation) ----------------
__device__ __align__(256) float g_x   [(size_t)NTOT * DD];
__device__ __align__(256) float g_P   [(size_t)NTOT * LSEQ];
__device__ __align__(256) float g_EW  [(size_t)BB * LSEQ * WSZ];
__device__ __align__(256) float g_HA4 [(size_t)NTOT * HA4_COLS];
__device__ __align__(256) float g_cat [(size_t)NTOT * CATK];   // [:,0:512]=nbr, [:,512:1024]=h1
__device__ __align__(256) float g_em  [(size_t)NTOT * DHE];
__device__ __align__(256) float g_XT  [(size_t)NTOT * DHE];
__device__ __align__(256) float g_S   [(size_t)BB * LSEQ * LSEQ];
__device__ __align__(256) float g_ATT [(size_t)NTOT * DHE];
__device__ __align__(256) float g_HID [(size_t)NTOT * HH];
__device__ __align__(256) float g_Wcat[(size_t)CATK * HH];     // [W_nbr ; W_self]

// speaker partition state
__device__ int g_cnt[2];
__device__ int g_cnt2[2];
__device__ int g_meta[4];        // M0, M0pad, M1, M1pad
__device__ int g_idx[MTILES * 128];

// ---------------- tf32 tensor-core SGEMM with cp.async + ldmatrix ----------------
// 128x128 block tile, BK=16, 4-stage cp.async pipeline, 256 thr = 8 warps (2m x 4n),
// warp tile 64x32 from m16n8k8 tf32 atoms. fp32 bits fed raw (hw truncates to tf32).
// A fragments via ldmatrix (tf32-as-b16-pairs); B scalar LDS (k-major) or ldmatrix (n-major).
#define APITCH 20
#define BPITCH 136
#define STG_FLOATS 2560          // max(128*20, 16*136)
#define NSTAGE 4
#define SMEM_BYTES (2 * NSTAGE * STG_FLOATS * 4)

__device__ __forceinline__ void cp16(uint32_t dst, const float* src) {
    asm volatile("cp.async.cg.shared.global [%0], [%1], 16;" :: "r"(dst), "l"(src));
}
__device__ __forceinline__ void ldm4(uint32_t* r, uint32_t a) {
    asm volatile("ldmatrix.sync.aligned.m8n8.x4.shared.b16 {%0,%1,%2,%3}, [%4];"
                 : "=r"(r[0]), "=r"(r[1]), "=r"(r[2]), "=r"(r[3]) : "r"(a));
}

// one BK=16 slab. abase/bbase: shared-state byte addresses; bptr: generic ptr (scalar path).
__device__ __forceinline__ void slab_mma(
    uint32_t abase, uint32_t bbase, const float* bptr, bool bkmaj,
    int wm, int wn, int lane, float acc[4][4][4])
{
    const int g = lane >> 2;
    const int t = lane & 3;
    // A ldmatrix lane addressing: matrix id m = lane>>3; row = (m&1)*8 + (lane&7); col4 = (m>>1)*4
    const int arow = ((lane >> 3) & 1) * 8 + (lane & 7);
    const int acol = ((lane >> 4) & 1) * 4;
    // BT-B ldmatrix: row = (m>>1)*8 + (lane&7); col4 = (m&1)*4
    const int brow = ((lane >> 4) & 1) * 8 + (lane & 7);
    const int bcol = ((lane >> 3) & 1) * 4;

    #pragma unroll
    for (int ks = 0; ks < 16; ks += 8) {
        uint32_t af[4][4], bf[4][2];
        #pragma unroll
        for (int mt = 0; mt < 4; mt++)
            ldm4(af[mt], abase + (uint32_t)(((wm * 64 + mt * 16 + arow) * APITCH + ks + acol) * 4));
        if (bkmaj) {
            #pragma unroll
            for (int nt = 0; nt < 4; nt++) {
                const int cn = wn * 32 + nt * 8;
                bf[nt][0] = __float_as_uint(bptr[(ks + t)     * BPITCH + cn + g]);
                bf[nt][1] = __float_as_uint(bptr[(ks + t + 4) * BPITCH + cn + g]);
            }
        } else {
            #pragma unroll
            for (int np = 0; np < 2; np++) {
                uint32_t r[4];
                ldm4(r, bbase + (uint32_t)(((wn * 32 + np * 16 + brow) * APITCH + ks + bcol) * 4));
                bf[2*np][0]   = r[0]; bf[2*np][1]   = r[1];
                bf[2*np+1][0] = r[2]; bf[2*np+1][1] = r[3];
            }
        }
        #pragma unroll
        for (int mt = 0; mt < 4; mt++)
            #pragma unroll
            for (int nt = 0; nt < 4; nt++) {
                asm volatile(
                    "mma.sync.aligned.m16n8k8.row.col.f32.tf32.tf32.f32 "
                    "{%0,%1,%2,%3}, {%4,%5,%6,%7}, {%8,%9}, {%0,%1,%2,%3};"
                    : "+f"(acc[mt][nt][0]), "+f"(acc[mt][nt][1]),
                      "+f"(acc[mt][nt][2]), "+f"(acc[mt][nt][3])
                    : "r"(af[mt][0]), "r"(af[mt][1]), "r"(af[mt][2]), "r"(af[mt][3]),
                      "r"(bf[nt][0]), "r"(bf[nt][1]));
            }
    }
}

template<int ACT, bool BT, bool ACC, bool BIAS>
__global__ __launch_bounds__(256, 2) void sgemm(
    const float* __restrict__ A, const float* __restrict__ B,
    float* __restrict__ C, const float* __restrict__ bias,
    int M, int N, int K, int lda, int ldb, int ldc,
    long long sA, long long sB, long long sC)
{
    A += (long long)blockIdx.z * sA;
    B += (long long)blockIdx.z * sB;
    C += (long long)blockIdx.z * sC;

    extern __shared__ float sm[];
    float* As = sm;
    float* Bs = sm + NSTAGE * STG_FLOATS;
    const uint32_t asb = (uint32_t)__cvta_generic_to_shared(As);
    const uint32_t bsb = (uint32_t)__cvta_generic_to_shared(Bs);

    const int tid  = threadIdx.x;
    const int lane = tid & 31;
    const int wid  = tid >> 5;
    const int wm   = wid & 1;
    const int wn   = wid >> 1;
    const int g    = lane >> 2;
    const int t    = lane & 3;

    const int m0 = blockIdx.y * 128;
    const int n0 = blockIdx.x * 128;

    const int ar = tid >> 2;
    const int ac = (tid & 3) * 4;
    const int bk = tid >> 5;
    const int bc = (tid & 31) * 4;

    float acc[4][4][4];
    #pragma unroll
    for (int i = 0; i < 4; i++)
        #pragma unroll
        for (int j = 0; j < 4; j++)
            #pragma unroll
            for (int e = 0; e < 4; e++) acc[i][j][e] = 0.f;

    const int KT = K / 16;

    auto fill = [&](int s, int k0) {
        const uint32_t ab = asb + (uint32_t)(s * STG_FLOATS * 4);
        cp16(ab + (ar * APITCH + ac) * 4,        A + (long long)(m0 + ar) * lda + k0 + ac);
        cp16(ab + ((ar + 64) * APITCH + ac) * 4, A + (long long)(m0 + ar + 64) * lda + k0 + ac);
        const uint32_t bb = bsb + (uint32_t)(s * STG_FLOATS * 4);
        if (!BT) {
            cp16(bb + (bk * BPITCH + bc) * 4,       B + (long long)(k0 + bk) * ldb + n0 + bc);
            cp16(bb + ((bk + 8) * BPITCH + bc) * 4, B + (long long)(k0 + bk + 8) * ldb + n0 + bc);
        } else {
            cp16(bb + (ar * APITCH + ac) * 4,        B + (long long)(n0 + ar) * ldb + k0 + ac);
            cp16(bb + ((ar + 64) * APITCH + ac) * 4, B + (long long)(n0 + ar + 64) * ldb + k0 + ac);
        }
    };

    fill(0, 0);  asm volatile("cp.async.commit_group;");
    fill(1, 16); asm volatile("cp.async.commit_group;");
    fill(2, 32); asm volatile("cp.async.commit_group;");

    for (int kt = 0; kt < KT; kt++) {
        asm volatile("cp.async.wait_group 2;" ::: "memory");
        __syncthreads();
        if (kt + 3 < KT) fill((kt + 3) & 3, (kt + 3) * 16);
        asm volatile("cp.async.commit_group;");

        const int so = (kt & 3) * STG_FLOATS;
        slab_mma(asb + (uint32_t)(so * 4), bsb + (uint32_t)(so * 4), Bs + so, !BT,
                 wm, wn, lane, acc);
    }

    #pragma unroll
    for (int mt = 0; mt < 4; mt++) {
        #pragma unroll
        for (int nt = 0; nt < 4; nt++) {
            const int col = n0 + wn * 32 + nt * 8 + t * 2;
            #pragma unroll
            for (int half = 0; half < 2; half++) {
                const long long row = m0 + wm * 64 + mt * 16 + g + half * 8;
                float v0 = acc[mt][nt][half * 2 + 0];
                float v1 = acc[mt][nt][half * 2 + 1];
                float* cp = C + row * ldc + col;
                if (ACC)  { float2 o = *(float2*)cp; v0 += o.x; v1 += o.y; }
                if (BIAS) { v0 += bias[col - n0 + n0]; v1 += bias[col + 1]; }
                if (ACT == 1) { v0 = fmaxf(v0, 0.f); v1 = fmaxf(v1, 0.f); }
                if (ACT == 2) { v0 = tanhf(v0); v1 = tanhf(v1); }
                *(float2*)cp = make_float2(v0, v1);
            }
        }
    }
}

// ---------------- speaker-split relation GEMM ----------------
__global__ __launch_bounds__(256, 2) void rel_gemm(const float* __restrict__ W_rel)
{
    const int M0    = g_meta[0];
    const int M0pad = g_meta[1];
    const int M1    = g_meta[2];
    const int M1pad = g_meta[3];

    const int m0 = blockIdx.y * 128;
    if (m0 >= M0pad + M1pad) return;
    const int grp = (m0 < M0pad) ? 0 : 1;

    extern __shared__ float sm[];
    float* As = sm;
    float* Bs = sm + NSTAGE * STG_FLOATS;
    __shared__ int sidx[128];
    const uint32_t asb = (uint32_t)__cvta_generic_to_shared(As);
    const uint32_t bsb = (uint32_t)__cvta_generic_to_shared(Bs);

    const int tid  = threadIdx.x;
    const int lane = tid & 31;
    const int wid  = tid >> 5;
    const int wm   = wid & 1;
    const int wn   = wid >> 1;
    const int g    = lane >> 2;
    const int t    = lane & 3;
    const int n0   = blockIdx.x * 128;
    const int j    = blockIdx.z;

    const float* B = W_rel + (long long)(grp * 4 + j) * DD * HH;

    if (tid < 128) sidx[tid] = g_idx[m0 + tid];

    const int ar = tid >> 2;
    const int ac = (tid & 3) * 4;
    const int bk = tid >> 5;
    const int bc = (tid & 31) * 4;
    const long long iA0 = g_idx[m0 + ar];
    const long long iA1 = g_idx[m0 + ar + 64];

    float acc[4][4][4];
    #pragma unroll
    for (int i = 0; i < 4; i++)
        #pragma unroll
        for (int jj = 0; jj < 4; jj++)
            #pragma unroll
            for (int e = 0; e < 4; e++) acc[i][jj][e] = 0.f;

    const int KT = DD / 16;

    auto fill = [&](int s, int k0) {
        const uint32_t ab = asb + (uint32_t)(s * STG_FLOATS * 4);
        cp16(ab + (ar * APITCH + ac) * 4,        g_x + iA0 * DD + k0 + ac);
        cp16(ab + ((ar + 64) * APITCH + ac) * 4, g_x + iA1 * DD + k0 + ac);
        const uint32_t bb = bsb + (uint32_t)(s * STG_FLOATS * 4);
        cp16(bb + (bk * BPITCH + bc) * 4,       B + (long long)(k0 + bk) * HH + n0 + bc);
        cp16(bb + ((bk + 8) * BPITCH + bc) * 4, B + (long long)(k0 + bk + 8) * HH + n0 + bc);
    };

    fill(0, 0);  asm volatile("cp.async.commit_group;");
    fill(1, 16); asm volatile("cp.async.commit_group;");
    fill(2, 32); asm volatile("cp.async.commit_group;");

    for (int kt = 0; kt < KT; kt++) {
        asm volatile("cp.async.wait_group 2;" ::: "memory");
        __syncthreads();
        if (kt + 3 < KT) fill((kt + 3) & 3, (kt + 3) * 16);
        asm volatile("cp.async.commit_group;");
        const int so = (kt & 3) * STG_FLOATS;
        slab_mma(asb + (uint32_t)(so * 4), bsb + (uint32_t)(so * 4), Bs + so, true,
                 wm, wn, lane, acc);
    }

    #pragma unroll
    for (int mt = 0; mt < 4; mt++) {
        #pragma unroll
        for (int nt = 0; nt < 4; nt++) {
            const int col = j * HH + n0 + wn * 32 + nt * 8 + t * 2;
            #pragma unroll
            for (int half = 0; half < 2; half++) {
                const int lr = wm * 64 + mt * 16 + g + half * 8;
                const int pr = m0 + lr;
                const bool valid = (grp == 0) ? (pr < M0) : (pr - M0pad < M1);
                if (valid) {
                    const long long node = sidx[lr];
                    *(float2*)(g_HA4 + node * HA4_COLS + col) =
                        make_float2(acc[mt][nt][half * 2], acc[mt][nt][half * 2 + 1]);
                }
            }
        }
    }
}

// ---------------- partition kernels ----------------
__global__ void part_count(const int* __restrict__ speakers)
{
    const int n = blockIdx.x * blockDim.x + threadIdx.x;
    if (n < MTILES * 128) g_idx[n] = 0;
    if (n < NTOT) {
        const int b = n >> 8, k = n & 255;
        atomicAdd(&g_cnt[speakers[k * BB + b]], 1);
    }
}
__global__ void part_meta()
{
    const int M0 = g_cnt[0], M1 = g_cnt[1];
    g_meta[0] = M0; g_meta[1] = ((M0 + 127) / 128) * 128;
    g_meta[2] = M1; g_meta[3] = ((M1 + 127) / 128) * 128;
    g_cnt[0] = 0; g_cnt[1] = 0;
    g_cnt2[0] = 0; g_cnt2[1] = 0;
}
__global__ void part_assign(const int* __restrict__ speakers)
{
    const int n = blockIdx.x * blockDim.x + threadIdx.x;
    if (n >= NTOT) return;
    const int b = n >> 8, k = n & 255;
    const int sp = speakers[k * BB + b];
    const int slot = atomicAdd(&g_cnt2[sp], 1);
    const int row = (sp == 0) ? slot : g_meta[1] + slot;
    g_idx[row] = n;
}

// ---------------- stage kernels ----------------
// x + em lower half
__global__ void make_x_kernel(const float* __restrict__ f)
{
    const int n = blockIdx.x;
    const int b = n >> 8, s = n & 255;
    const float* src = f + ((long long)s * BB + b) * DD;
    for (int d = threadIdx.x; d < DD; d += blockDim.x) {
        const float v = src[d];
        g_x[(long long)n * DD + d] = v;
        g_em[(long long)n * DHE + d] = v;
    }
}

__global__ void build_wcat(const float* __restrict__ Wn, const float* __restrict__ Ws)
{
    const int i = blockIdx.x * blockDim.x + threadIdx.x;
    if (i < HH * HH) {
        g_Wcat[i] = Wn[i];
        g_Wcat[HH * HH + i] = Ws[i];
    }
}

__global__ void edge_softmax_kernel()
{
    __shared__ float red[256];
    const int bi = blockIdx.x;
    const int b = bi >> 8, i = bi & 255;
    const int s = threadIdx.x;

    const float v = g_P[((long long)(b * 256 + s)) * LSEQ + i];

    red[s] = v; __syncthreads();
    for (int o = 128; o > 0; o >>= 1) { if (s < o) red[s] = fmaxf(red[s], red[s + o]); __syncthreads(); }
    const float m = red[0]; __syncthreads();

    const float e = __expf(v - m);
    red[s] = e; __syncthreads();
    for (int o = 128; o > 0; o >>= 1) { if (s < o) red[s] += red[s + o]; __syncthreads(); }
    const float Z = red[0]; __syncthreads();

    const bool inwin = (s >= i - WINR) && (s <= i + WINR);
    red[s] = inwin ? e : 0.f; __syncthreads();
    for (int o = 128; o > 0; o >>= 1) { if (s < o) red[s] += red[s + o]; __syncthreads(); }
    const float Swin = red[0];

    const float denom = Swin + 1e-10f * (Z - Swin);
    if (inwin)
        g_EW[(long long)bi * WSZ + (s - i + WINR)] = e / denom;
    if (s < WSZ) {
        const int k = i - WINR + s;
        if (k < 0 || k >= LSEQ) g_EW[(long long)bi * WSZ + s] = 0.f;
    }
}

// in-place: g_cat[n,512+h] = root(n,h) + sum_win w * HA4
__global__ __launch_bounds__(512) void rgcn_agg_kernel(const int* __restrict__ speakers)
{
    const int n = blockIdx.x;
    const int b = n >> 8, k = n & 255;
    const int h = threadIdx.x;

    __shared__ float w[WSZ];
    const int lo = max(k - WINR, 0), hi = min(k + WINR, LSEQ - 1);
    const int cnt = hi - lo + 1;
    if (h < cnt) {
        const int i = lo + h;
        w[h] = g_EW[((long long)(b * 256 + i)) * WSZ + (k - i + WINR)];
    }
    __syncthreads();

    const int spk = speakers[k * BB + b];
    float acc = g_cat[(long long)n * CATK + HH + h];
    for (int t = 0; t < cnt; t++) {
        const int i = lo + t;
        const int j = spk * 2 + ((i < k) ? 0 : 1);
        acc += w[t] * g_HA4[((long long)(b * 256 + i)) * HA4_COLS + j * HH + h];
    }
    g_cat[(long long)n * CATK + HH + h] = acc;
}

// sliding-window sum of h1 (cat upper) -> cat lower
__global__ __launch_bounds__(512) void nbr_kernel()
{
    const int b = blockIdx.x;
    const int kstart = blockIdx.y * 64;
    const int h = threadIdx.x;

    float run = 0.f;
    const int lo = max(kstart - WINR, 0), hi = min(kstart + WINR, LSEQ - 1);
    for (int j = lo; j <= hi; j++) run += g_cat[((long long)(b * 256 + j)) * CATK + HH + h];
    g_cat[((long long)(b * 256 + kstart)) * CATK + h] = run;

    for (int k = kstart + 1; k < kstart + 64; k++) {
        const int add = k + WINR, sub = k - WINR - 1;
        if (add < LSEQ) run += g_cat[((long long)(b * 256 + add)) * CATK + HH + h];
        if (sub >= 0)   run -= g_cat[((long long)(b * 256 + sub)) * CATK + HH + h];
        g_cat[((long long)(b * 256 + k)) * CATK + h] = run;
    }
}

__global__ void softmax_rows_kernel()
{
    __shared__ float red[256];
    const long long r = blockIdx.x;
    const int s = threadIdx.x;
    const float v = g_S[r * 256 + s];

    red[s] = v; __syncthreads();
    for (int o = 128; o > 0; o >>= 1) { if (s < o) red[s] = fmaxf(red[s], red[s + o]); __syncthreads(); }
    const float m = red[0]; __syncthreads();
    const float e = __expf(v - m);
    red[s] = e; __syncthreads();
    for (int o = 128; o > 0; o >>= 1) { if (s < o) red[s] += red[s + o]; __syncthreads(); }
    g_S[r * 256 + s] = e / red[0];
}

__global__ void final_kernel(const float* __restrict__ W_fc,
                             const float* __restrict__ b_fc,
                             float* __restrict__ out)
{
    const int gwarp = (blockIdx.x * blockDim.x + threadIdx.x) >> 5;
    const int lane = threadIdx.x & 31;
    if (gwarp >= NTOT) return;

    float p[CC] = {0.f, 0.f, 0.f, 0.f, 0.f, 0.f};
    #pragma unroll
    for (int j = 0; j < 16; j++) {
        const int hidx = lane + j * 32;
        const float hv = g_HID[(long long)gwarp * HH + hidx];
        const float* wr = W_fc + (long long)hidx * CC;
        #pragma unroll
        for (int c = 0; c < CC; c++) p[c] += hv * wr[c];
    }
    #pragma unroll
    for (int o = 16; o > 0; o >>= 1)
        #pragma unroll
        for (int c = 0; c < CC; c++) p[c] += __shfl_down_sync(0xffffffffu, p[c], o);

    if (lane == 0) {
        float lg[CC], m = -1e30f;
        #pragma unroll
        for (int c = 0; c < CC; c++) { lg[c] = p[c] + b_fc[c]; m = fmaxf(m, lg[c]); }
        float ssum = 0.f;
        #pragma unroll
        for (int c = 0; c < CC; c++) ssum += __expf(lg[c] - m);
        const float lse = m + logf(ssum);
        #pragma unroll
        for (int c = 0; c < CC; c++) out[(long long)gwarp * CC + c] = lg[c] - lse;
    }
}

// ---------------- host orchestration ----------------
extern "C" void kernel_launch(void* const* d_in, const int* in_sizes, int n_in,
                              void* d_out, int out_size)
{
    const float* features = (const float*)d_in[0];
    const float* Wscalar  = (const float*)d_in[1];
    const float* W_rel    = (const float*)d_in[2];
    const float* W_root   = (const float*)d_in[3];
    const float* b_rgcn   = (const float*)d_in[4];
    const float* W_nbr    = (const float*)d_in[5];
    const float* W_self   = (const float*)d_in[6];
    const float* b_gc     = (const float*)d_in[7];
    const float* W_match  = (const float*)d_in[8];
    const float* b_match  = (const float*)d_in[9];
    const float* W_lin    = (const float*)d_in[10];
    const float* b_lin    = (const float*)d_in[11];
    const float* W_fc     = (const float*)d_in[12];
    const float* b_fc     = (const float*)d_in[13];
    const int*   speakers = (const int*)  d_in[14];
    float* out = (float*)d_out;

    float *x, *P, *cat, *em, *XT, *S, *ATT, *HID, *Wcat;
    cudaGetSymbolAddress((void**)&x,    g_x);
    cudaGetSymbolAddress((void**)&P,    g_P);
    cudaGetSymbolAddress((void**)&cat,  g_cat);
    cudaGetSymbolAddress((void**)&em,   g_em);
    cudaGetSymbolAddress((void**)&XT,   g_XT);
    cudaGetSymbolAddress((void**)&S,    g_S);
    cudaGetSymbolAddress((void**)&ATT,  g_ATT);
    cudaGetSymbolAddress((void**)&HID,  g_HID);
    cudaGetSymbolAddress((void**)&Wcat, g_Wcat);

    cudaFuncSetAttribute(sgemm<0,false,false,false>, cudaFuncAttributeMaxDynamicSharedMemorySize, SMEM_BYTES);
    cudaFuncSetAttribute(sgemm<0,false,false,true>,  cudaFuncAttributeMaxDynamicSharedMemorySize, SMEM_BYTES);
    cudaFuncSetAttribute(sgemm<2,true,false,false>,  cudaFuncAttributeMaxDynamicSharedMemorySize, SMEM_BYTES);
    cudaFuncSetAttribute(sgemm<1,false,false,true>,  cudaFuncAttributeMaxDynamicSharedMemorySize, SMEM_BYTES);
    cudaFuncSetAttribute(rel_gemm, cudaFuncAttributeMaxDynamicSharedMemorySize, SMEM_BYTES);

    // 0. transpose -> x/em-low; Wcat; speaker partition
    make_x_kernel<<<NTOT, 256>>>(features);
    build_wcat<<<(HH*HH + 255)/256, 256>>>(W_nbr, W_self);
    part_count<<<(MTILES * 128 + 255) / 256, 256>>>(speakers);
    part_meta<<<1, 1>>>();
    part_assign<<<(NTOT + 255) / 256, 256>>>(speakers);

    // 1. P = x @ Wscalar
    sgemm<0,false,false,false><<<dim3(LSEQ/128, NTOT/128), 256, SMEM_BYTES>>>(
        x, Wscalar, P, nullptr, NTOT, LSEQ, DD, DD, LSEQ, LSEQ, 0, 0, 0);

    // 2. edge softmax
    edge_softmax_kernel<<<BB * LSEQ, 256>>>();

    // 3. root term -> cat upper half; speaker-split relation transforms -> HA4
    sgemm<0,false,false,true><<<dim3(HH/128, NTOT/128), 256, SMEM_BYTES>>>(
        x, W_root, cat + HH, b_rgcn, NTOT, HH, DD, DD, HH, CATK, 0, 0, 0);
    rel_gemm<<<dim3(HH/128, MTILES, 4), 256, SMEM_BYTES>>>(W_rel);

    // 4. RGCN aggregation in place (cat upper = h1)
    rgcn_agg_kernel<<<NTOT, 512>>>(speakers);

    // 5. GraphConv fused: nbr -> cat lower; h2 = cat @ [W_nbr;W_self] + b_gc -> em upper
    nbr_kernel<<<dim3(BB, LSEQ/64), 512>>>();
    sgemm<0,false,false,true><<<dim3(HH/128, NTOT/128), 256, SMEM_BYTES>>>(
        cat, Wcat, em + DD, b_gc, NTOT, HH, CATK, CATK, HH, DHE, 0, 0, 0);

    // 6. XT = em @ W_match + b_match
    sgemm<0,false,false,true><<<dim3(DHE/128, NTOT/128), 256, SMEM_BYTES>>>(
        em, W_match, XT, b_match, NTOT, DHE, DHE, DHE, DHE, DHE, 0, 0, 0);

    // 7. S = tanh(XT @ em^T) batched; softmax; ATT = S @ em
    sgemm<2,true,false,false><<<dim3(LSEQ/128, LSEQ/128, BB), 256, SMEM_BYTES>>>(
        XT, em, S, nullptr, LSEQ, LSEQ, DHE, DHE, DHE, LSEQ,
        (long long)LSEQ * DHE, (long long)LSEQ * DHE, (long long)LSEQ * LSEQ);
    softmax_rows_kernel<<<BB * LSEQ, 256>>>();
    sgemm<0,false,false,false><<<dim3(DHE/128, LSEQ/128, BB), 256, SMEM_BYTES>>>(
        S, em, ATT, nullptr, LSEQ, DHE, LSEQ, LSEQ, DHE, DHE,
        (long long)LSEQ * LSEQ, (long long)LSEQ * DHE, (long long)LSEQ * DHE);

    // 8. HID = relu(ATT @ W_lin + b_lin)
    sgemm<1,false,false,true><<<dim3(HH/128, NTOT/128), 256, SMEM_BYTES>>>(
        ATT, W_lin, HID, b_lin, NTOT, HH, DHE, DHE, HH, HH, 0, 0, 0);

    // 9. logits + log_softmax -> out
    final_kernel<<<(NTOT * 32 + 127) / 128, 128>>>(W_fc, b_fc, out);
}